// round 2
// baseline (speedup 1.0000x reference)
#include <cuda_runtime.h>
#include <math.h>

#define NN  256   // n_res (both residue axes)
#define CIN 128   // c_q
#define NH  4     // heads
#define HD  32    // per-head dim
#define NE  128   // H*D

// Scratch (allocation-free rule: __device__ globals)
__device__ float g_Q[NN*NH*NN*HD];   // [n][h][q][d], pre-scaled
__device__ float g_K[NN*NH*NN*HD];   // [n][h][k][d]
__device__ float g_V[NN*NH*NN*HD];   // [n][h][k][d]
__device__ float g_G[NN*NN*NE];      // sigmoid gate [n][q][e]
__device__ float g_O[NN*NN*NE];      // gated attention out [n][q][e]

// ---------------------------------------------------------------------------
// Kernel 1: 4 projections as GEMMs.  rows = n*256+q (65536), cols = h*32+d (128), K = 128
// blockIdx.y selects projection: 0=Q(scaled) 1=K 2=V 3=gate(sigmoid+bias)
// Block: 128 threads; 32 rows x 128 cols per block; thread = 8 rows x 4 cols.
// ---------------------------------------------------------------------------
__global__ __launch_bounds__(128) void proj_kernel(
    const float* __restrict__ qx, const float* __restrict__ kvx,
    const float* __restrict__ wq, const float* __restrict__ wk,
    const float* __restrict__ wv, const float* __restrict__ wg,
    const float* __restrict__ bg)
{
    __shared__ float ws[128][33];   // W[j][c-chunk], pad 33 -> conflict-free
    __shared__ float xs[32][128];   // X rows (reads are broadcast)

    const int z = blockIdx.y;
    const float* X = (z == 0 || z == 3) ? qx : kvx;
    const float* W = (z == 0) ? wq : (z == 1) ? wk : (z == 2) ? wv : wg;

    const int tid = threadIdx.x;
    const int r0  = blockIdx.x * 32;
    const int tx  = tid & 31;       // col lane: cols j = tx + 32k
    const int ty  = tid >> 5;       // row group: rows ty*8 .. ty*8+7

    #pragma unroll 4
    for (int i = 0; i < 32; i++)
        xs[i][tid] = X[(size_t)(r0 + i) * CIN + tid];

    float acc[8][4];
    #pragma unroll
    for (int r = 0; r < 8; r++)
        #pragma unroll
        for (int k = 0; k < 4; k++) acc[r][k] = 0.f;

    for (int cc = 0; cc < 128; cc += 32) {
        __syncthreads();
        #pragma unroll 8
        for (int i = 0; i < 32; i++) {
            int lin = i * 128 + tid;          // j = lin>>5, cl = lin&31
            ws[lin >> 5][lin & 31] = W[(lin >> 5) * CIN + cc + (lin & 31)];
        }
        __syncthreads();
        #pragma unroll
        for (int cl = 0; cl < 32; cl++) {
            float w0 = ws[tx][cl], w1 = ws[tx + 32][cl];
            float w2 = ws[tx + 64][cl], w3 = ws[tx + 96][cl];
            #pragma unroll
            for (int r = 0; r < 8; r++) {
                float xv = xs[ty * 8 + r][cc + cl];
                acc[r][0] += xv * w0; acc[r][1] += xv * w1;
                acc[r][2] += xv * w2; acc[r][3] += xv * w3;
            }
        }
    }

    const float SCALE = 0.17677669529663687f;  // 1/sqrt(32)
    #pragma unroll
    for (int r = 0; r < 8; r++) {
        int rid = r0 + ty * 8 + r;
        int n = rid >> 8, qq = rid & 255;
        #pragma unroll
        for (int k = 0; k < 4; k++) {
            float v = acc[r][k];
            // col j = tx + 32k -> h = k, d = tx
            size_t hidx = ((size_t)(n * NH + k) * NN + qq) * HD + tx;
            if (z == 0)      g_Q[hidx] = v * SCALE;
            else if (z == 1) g_K[hidx] = v;
            else if (z == 2) g_V[hidx] = v;
            else {
                float b = bg[k * HD + tx];
                g_G[(size_t)rid * NE + k * HD + tx] = 1.f / (1.f + __expf(-(v + b)));
            }
        }
    }
}

// ---------------------------------------------------------------------------
// Kernel 2: attention per (n, h, q-tile of 32). 256 threads = 32 q x 8 kchunk.
// Two-phase over ONE 36KB static smem tile: phase A = K (scores+softmax),
// phase B = V (AV accumulate). Per-thread scores s[32] carry state across.
// ---------------------------------------------------------------------------
__global__ __launch_bounds__(256, 2) void attn_kernel(
    const float* __restrict__ mb,   // mask_bias   [n][k]
    const float* __restrict__ tb)   // triangle    [h][q][k]
{
    __shared__ float4 T4[256 * 9];  // 36864 B, K then V

    const int q0 = blockIdx.x * 32;
    const int h  = blockIdx.y;
    const int n  = blockIdx.z;
    const int tid = threadIdx.x;
    const int q  = tid >> 3;        // 0..31
    const int t  = tid & 7;         // k-chunk id
    const int qg = q0 + q;

    const float4* gK4 = (const float4*)g_K + (size_t)(n * NH + h) * NN * 8;
    const float4* gV4 = (const float4*)g_V + (size_t)(n * NH + h) * NN * 8;
    const float4* gQ4 = (const float4*)g_Q + (size_t)(n * NH + h) * NN * 8;

    // ---- phase A: K tile, scores, softmax ----
    #pragma unroll
    for (int i = 0; i < 8; i++) {
        int lin = i * 256 + tid;    // kk = lin>>3, d4 = lin&7
        T4[(lin >> 3) * 9 + (lin & 7)] = gK4[lin];
    }
    float4 qreg[8];
    #pragma unroll
    for (int d4 = 0; d4 < 8; d4++) qreg[d4] = gQ4[qg * 8 + d4];
    __syncthreads();

    const float* mrow = mb + n * NN;
    const float* trow = tb + ((size_t)h * NN + qg) * NN;

    float s[32];
    float m = -1e30f;
    #pragma unroll
    for (int i = 0; i < 32; i++) {
        int kk = t + 8 * i;                  // distinct banks across lanes
        const float4* kr = T4 + kk * 9;
        float a = 0.f;
        #pragma unroll
        for (int d4 = 0; d4 < 8; d4++) {
            float4 kv = kr[d4];
            a += qreg[d4].x * kv.x + qreg[d4].y * kv.y
               + qreg[d4].z * kv.z + qreg[d4].w * kv.w;
        }
        a += mrow[kk] + trow[kk];
        s[i] = a;
        m = fmaxf(m, a);
    }
    #pragma unroll
    for (int off = 1; off < 8; off <<= 1)
        m = fmaxf(m, __shfl_xor_sync(0xffffffffu, m, off));
    float l = 0.f;
    #pragma unroll
    for (int i = 0; i < 32; i++) { s[i] = __expf(s[i] - m); l += s[i]; }
    #pragma unroll
    for (int off = 1; off < 8; off <<= 1)
        l += __shfl_xor_sync(0xffffffffu, l, off);
    float inv = 1.f / l;

    // ---- phase B: overwrite smem with V, accumulate AV ----
    __syncthreads();                       // all lanes done reading K
    #pragma unroll
    for (int i = 0; i < 8; i++) {
        int lin = i * 256 + tid;
        T4[(lin >> 3) * 9 + (lin & 7)] = gV4[lin];
    }
    __syncthreads();

    float4 po[8];
    #pragma unroll
    for (int d4 = 0; d4 < 8; d4++) po[d4] = make_float4(0.f, 0.f, 0.f, 0.f);
    #pragma unroll
    for (int i = 0; i < 32; i++) {
        int kk = t + 8 * i;
        const float4* vr = T4 + kk * 9;
        float p = s[i];
        #pragma unroll
        for (int d4 = 0; d4 < 8; d4++) {
            float4 vv = vr[d4];
            po[d4].x += p * vv.x; po[d4].y += p * vv.y;
            po[d4].z += p * vv.z; po[d4].w += p * vv.w;
        }
    }
    // reduce partial O across the 8 lanes sharing this q
    #pragma unroll
    for (int off = 1; off < 8; off <<= 1) {
        #pragma unroll
        for (int d4 = 0; d4 < 8; d4++) {
            po[d4].x += __shfl_xor_sync(0xffffffffu, po[d4].x, off);
            po[d4].y += __shfl_xor_sync(0xffffffffu, po[d4].y, off);
            po[d4].z += __shfl_xor_sync(0xffffffffu, po[d4].z, off);
            po[d4].w += __shfl_xor_sync(0xffffffffu, po[d4].w, off);
        }
    }
    // thread t owns d = 4t..4t+3 ; apply 1/l and gate, store gated O
    int rid = n * NN + qg;
    const float4* gG4 = (const float4*)g_G;
    float4*       gO4 = (float4*)g_O;
    float4 gt = gG4[(size_t)rid * 32 + h * 8 + t];
    float4 r  = po[t];
    r.x *= inv * gt.x; r.y *= inv * gt.y; r.z *= inv * gt.z; r.w *= inv * gt.w;
    gO4[(size_t)rid * 32 + h * 8 + t] = r;
}

// ---------------------------------------------------------------------------
// Kernel 3: output projection  out[rid][c] = sum_e O[rid][e]*wo[c][e] + bo[c]
// Same blocking as proj_kernel.
// ---------------------------------------------------------------------------
__global__ __launch_bounds__(128) void out_kernel(
    const float* __restrict__ wo, const float* __restrict__ bo,
    float* __restrict__ out)
{
    __shared__ float ws[128][33];
    __shared__ float xs[32][128];

    const int tid = threadIdx.x;
    const int r0  = blockIdx.x * 32;
    const int tx  = tid & 31, ty = tid >> 5;

    #pragma unroll 4
    for (int i = 0; i < 32; i++)
        xs[i][tid] = g_O[(size_t)(r0 + i) * NE + tid];

    float acc[8][4];
    #pragma unroll
    for (int r = 0; r < 8; r++)
        #pragma unroll
        for (int k = 0; k < 4; k++) acc[r][k] = 0.f;

    for (int cc = 0; cc < 128; cc += 32) {
        __syncthreads();
        #pragma unroll 8
        for (int i = 0; i < 32; i++) {
            int lin = i * 128 + tid;
            ws[lin >> 5][lin & 31] = wo[(lin >> 5) * NE + cc + (lin & 31)];
        }
        __syncthreads();
        #pragma unroll
        for (int cl = 0; cl < 32; cl++) {
            float w0 = ws[tx][cl], w1 = ws[tx + 32][cl];
            float w2 = ws[tx + 64][cl], w3 = ws[tx + 96][cl];
            #pragma unroll
            for (int r = 0; r < 8; r++) {
                float xv = xs[ty * 8 + r][cc + cl];
                acc[r][0] += xv * w0; acc[r][1] += xv * w1;
                acc[r][2] += xv * w2; acc[r][3] += xv * w3;
            }
        }
    }

    #pragma unroll
    for (int r = 0; r < 8; r++) {
        int rid = r0 + ty * 8 + r;
        #pragma unroll
        for (int k = 0; k < 4; k++) {
            int c = tx + 32 * k;
            out[(size_t)rid * CIN + c] = acc[r][k] + bo[c];
        }
    }
}

// ---------------------------------------------------------------------------
extern "C" void kernel_launch(void* const* d_in, const int* in_sizes, int n_in,
                              void* d_out, int out_size)
{
    const float* qx  = (const float*)d_in[0];
    const float* kvx = (const float*)d_in[1];
    const float* mb  = (const float*)d_in[2];
    const float* tb  = (const float*)d_in[3];
    const float* wq  = (const float*)d_in[4];
    const float* wk  = (const float*)d_in[5];
    const float* wv  = (const float*)d_in[6];
    const float* wg  = (const float*)d_in[7];
    const float* bg  = (const float*)d_in[8];
    const float* wo  = (const float*)d_in[9];
    const float* bo  = (const float*)d_in[10];
    float* out = (float*)d_out;

    proj_kernel<<<dim3(65536 / 32, 4), 128>>>(qx, kvx, wq, wk, wv, wg, bg);
    attn_kernel<<<dim3(NN / 32, NH, NN), 256>>>(mb, tb);
    out_kernel<<<65536 / 32, 128>>>(wo, bo, out);
}

// round 4
// speedup vs baseline: 1.9898x; 1.9898x over previous
#include <cuda_runtime.h>
#include <cuda_bf16.h>
#include <cstdint>
#include <math.h>

#define NN  256
#define CIN 128
#define NH  4
#define HD  32
#define NE  128

// Scratch (allocation-free rule)
__device__ float g_Q[NN*NH*NN*HD];   // [n][h][q][d], pre-scaled
__device__ float g_K[NN*NH*NN*HD];   // [n][h][k][d]
__device__ float g_V[NN*NH*NN*HD];   // [n][h][k][d]
__device__ float g_G[NN*NN*NE];      // sigmoid gate [rid][e]
__device__ float g_O[NN*NN*NE];      // gated attention out [rid][e]
__device__ __align__(16) __nv_bfloat16 g_Wh[5][128][136];  // wq,wk,wv,wg,wo hi
__device__ __align__(16) __nv_bfloat16 g_Wl[5][128][136];  // lo

// ---------------------------------------------------------------------------
// helpers
// ---------------------------------------------------------------------------
__device__ __forceinline__ uint32_t smem_u32(const void* p) {
    uint32_t a;
    asm("{ .reg .u64 t; cvta.to.shared.u64 t, %1; cvt.u32.u64 %0, t; }"
        : "=r"(a) : "l"(p));
    return a;
}

__device__ __forceinline__ void ldsm_x4(uint32_t* r, uint32_t addr) {
    asm volatile("ldmatrix.sync.aligned.m8n8.x4.shared.b16 {%0,%1,%2,%3}, [%4];"
        : "=r"(r[0]), "=r"(r[1]), "=r"(r[2]), "=r"(r[3]) : "r"(addr));
}

__device__ __forceinline__ void mma_bf16(float* d, const uint32_t* a, const uint32_t* b) {
    asm volatile(
        "mma.sync.aligned.m16n8k16.row.col.f32.bf16.bf16.f32 "
        "{%0,%1,%2,%3}, {%4,%5,%6,%7}, {%8,%9}, {%0,%1,%2,%3};"
        : "+f"(d[0]), "+f"(d[1]), "+f"(d[2]), "+f"(d[3])
        : "r"(a[0]), "r"(a[1]), "r"(a[2]), "r"(a[3]), "r"(b[0]), "r"(b[1]));
}

// split two fp32 into packed bf16 hi-word and lo-word (elem0 in low half)
__device__ __forceinline__ void split2(float a, float b, uint32_t& h, uint32_t& l) {
    __nv_bfloat16 ha = __float2bfloat16(a), hb = __float2bfloat16(b);
    float la = a - __bfloat162float(ha), lb = b - __bfloat162float(hb);
    __nv_bfloat16 lA = __float2bfloat16(la), lB = __float2bfloat16(lb);
    h = (uint32_t)__bfloat16_as_ushort(ha) | ((uint32_t)__bfloat16_as_ushort(hb) << 16);
    l = (uint32_t)__bfloat16_as_ushort(lA) | ((uint32_t)__bfloat16_as_ushort(lB) << 16);
}

// convert 8 consecutive floats -> uint4 hi + uint4 lo
__device__ __forceinline__ void stage8(const float* s, void* dh, void* dl) {
    uint32_t h[4], l[4];
    #pragma unroll
    for (int p = 0; p < 4; p++) split2(s[2*p], s[2*p+1], h[p], l[p]);
    *(uint4*)dh = make_uint4(h[0], h[1], h[2], h[3]);
    *(uint4*)dl = make_uint4(l[0], l[1], l[2], l[3]);
}

// ---------------------------------------------------------------------------
// Kernel 0: convert 5 weight matrices (each [128][128], contraction contiguous)
// into bf16 hi/lo with padded row stride 136 halves.
// ---------------------------------------------------------------------------
__global__ __launch_bounds__(256) void convw_kernel(
    const float* __restrict__ wq, const float* __restrict__ wk,
    const float* __restrict__ wv, const float* __restrict__ wg,
    const float* __restrict__ wo)
{
    int m = blockIdx.x;
    const float* src = (m == 0) ? wq : (m == 1) ? wk : (m == 2) ? wv : (m == 3) ? wg : wo;
    for (int idx = threadIdx.x; idx < 128 * 64; idx += 256) {
        int r = idx >> 6, cp = (idx & 63) * 2;
        uint32_t h, l;
        split2(src[r * 128 + cp], src[r * 128 + cp + 1], h, l);
        *(uint32_t*)&g_Wh[m][r][cp] = h;
        *(uint32_t*)&g_Wl[m][r][cp] = l;
    }
}

// ---------------------------------------------------------------------------
// Kernel 1: fused 4 projections. grid=512 (128-row tiles), block=256 (8 warps).
// smem: XQ hi/lo, XKV hi/lo, W hi/lo, each [128][136] bf16 (34816 B).
// ---------------------------------------------------------------------------
#define PJ_XQH 0
#define PJ_XQL 34816
#define PJ_XKH 69632
#define PJ_XKL 104448
#define PJ_WH  139264
#define PJ_WL  174080
#define PJ_SMEM 208896

__global__ __launch_bounds__(256) void mma_proj_kernel(
    const float* __restrict__ qx, const float* __restrict__ kvx,
    const float* __restrict__ bg)
{
    extern __shared__ __align__(16) char smem[];
    const int tid = threadIdx.x, w = tid >> 5, lane = tid & 31;
    const int r0 = blockIdx.x * 128;

    // stage X tiles (qx, kvx): thread -> (row = tid/2, 64 cols)
    {
        int r = tid >> 1, c0 = (tid & 1) * 64;
        const float* xq = qx  + (size_t)(r0 + r) * CIN + c0;
        const float* xk = kvx + (size_t)(r0 + r) * CIN + c0;
        __nv_bfloat16* qh = (__nv_bfloat16*)(smem + PJ_XQH) + r * 136 + c0;
        __nv_bfloat16* ql = (__nv_bfloat16*)(smem + PJ_XQL) + r * 136 + c0;
        __nv_bfloat16* kh = (__nv_bfloat16*)(smem + PJ_XKH) + r * 136 + c0;
        __nv_bfloat16* kl = (__nv_bfloat16*)(smem + PJ_XKL) + r * 136 + c0;
        float buf[8];
        #pragma unroll
        for (int i = 0; i < 64; i += 8) {
            *(float4*)&buf[0] = *(const float4*)(xq + i);
            *(float4*)&buf[4] = *(const float4*)(xq + i + 4);
            stage8(buf, qh + i, ql + i);
            *(float4*)&buf[0] = *(const float4*)(xk + i);
            *(float4*)&buf[4] = *(const float4*)(xk + i + 4);
            stage8(buf, kh + i, kl + i);
        }
    }

    const uint32_t sb = smem_u32(smem);
    const int lt = lane >> 3, lr = lane & 7;
    const uint32_t a_off = ((w * 16 + ((lt & 1) ? 8 : 0) + lr) * 136 + ((lt & 2) ? 8 : 0)) * 2;
    const uint32_t b_off = ((((lt & 2) ? 8 : 0) + lr) * 136 + ((lt & 1) ? 8 : 0)) * 2;
    const float SCALE = 0.17677669529663687f;

    for (int mode = 0; mode < 4; mode++) {
        __syncthreads();
        // copy pre-converted W into smem (L2-resident)
        {
            const uint4* sh = (const uint4*)g_Wh[mode];
            const uint4* sl = (const uint4*)g_Wl[mode];
            uint4* dh = (uint4*)(smem + PJ_WH);
            uint4* dl = (uint4*)(smem + PJ_WL);
            for (int i = tid; i < 2176; i += 256) { dh[i] = sh[i]; dl[i] = sl[i]; }
        }
        __syncthreads();

        const uint32_t Xh = sb + ((mode == 0 || mode == 3) ? PJ_XQH : PJ_XKH);

        float acc[16][4];
        #pragma unroll
        for (int f = 0; f < 16; f++)
            #pragma unroll
            for (int i = 0; i < 4; i++) acc[f][i] = 0.f;

        #pragma unroll
        for (int s = 0; s < 3; s++) {
            uint32_t Ab = ((s == 2) ? Xh + 34816 : Xh) + a_off;
            uint32_t Bb = sb + ((s == 1) ? PJ_WL : PJ_WH) + b_off;
            #pragma unroll
            for (int k = 0; k < 8; k++) {
                uint32_t a[4];
                ldsm_x4(a, Ab + k * 32);
                #pragma unroll
                for (int ng = 0; ng < 8; ng++) {
                    uint32_t b[4];
                    ldsm_x4(b, Bb + ng * 16 * 272 + k * 32);
                    mma_bf16(acc[2 * ng],     a, b);
                    mma_bf16(acc[2 * ng + 1], a, b + 2);
                }
            }
        }

        // epilogue
        const int rid_lo = r0 + w * 16 + (lane >> 2);
        const int rid_hi = rid_lo + 8;
        const int n_lo = rid_lo >> 8, q_lo = rid_lo & 255;
        const int n_hi = rid_hi >> 8, q_hi = rid_hi & 255;

        if (mode < 3) {
            float sc = (mode == 0) ? SCALE : 1.f;
            float* dstb = (mode == 0) ? g_Q : (mode == 1) ? g_K : g_V;
            #pragma unroll
            for (int f = 0; f < 16; f++) {
                int j = f * 8 + 2 * (lane & 3);
                int hh = j >> 5, d = j & 31;
                float2 v0 = {acc[f][0] * sc, acc[f][1] * sc};
                float2 v1 = {acc[f][2] * sc, acc[f][3] * sc};
                *(float2*)(dstb + ((size_t)(n_lo * NH + hh) * NN + q_lo) * HD + d) = v0;
                *(float2*)(dstb + ((size_t)(n_hi * NH + hh) * NN + q_hi) * HD + d) = v1;
            }
        } else {
            #pragma unroll
            for (int f = 0; f < 16; f++) {
                int j = f * 8 + 2 * (lane & 3);
                float b0 = bg[j], b1 = bg[j + 1];
                float2 v0 = {1.f / (1.f + __expf(-(acc[f][0] + b0))),
                             1.f / (1.f + __expf(-(acc[f][1] + b1)))};
                float2 v1 = {1.f / (1.f + __expf(-(acc[f][2] + b0))),
                             1.f / (1.f + __expf(-(acc[f][3] + b1)))};
                *(float2*)(g_G + (size_t)rid_lo * NE + j) = v0;
                *(float2*)(g_G + (size_t)rid_hi * NE + j) = v1;
            }
        }
    }
}

// ---------------------------------------------------------------------------
// Kernel 2: attention, FA2-style. grid=(2, NH, NN), block=256 (8 warps x 16 q).
// smem: Q hi/lo [128][40], K hi/lo [256][40], V^T hi/lo [32][264].
// ---------------------------------------------------------------------------
#define AT_QH 0
#define AT_QL 10240
#define AT_KH 20480
#define AT_KL 40960
#define AT_VH 61440
#define AT_VL 78336
#define AT_SMEM 95232

__global__ __launch_bounds__(256, 2) void mma_attn_kernel(
    const float* __restrict__ mb, const float* __restrict__ tb)
{
    extern __shared__ __align__(16) char smem[];
    const int tid = threadIdx.x, w = tid >> 5, lane = tid & 31;
    const int q0 = blockIdx.x * 128;
    const int h  = blockIdx.y;
    const int n  = blockIdx.z;

    const float* baseQ = g_Q + (size_t)(n * NH + h) * NN * HD;
    const float* baseK = g_K + (size_t)(n * NH + h) * NN * HD;
    const float* baseV = g_V + (size_t)(n * NH + h) * NN * HD;

    // --- stage Q (rows q0..q0+127) ---
    {
        int r = tid >> 1, c0 = (tid & 1) * 16;
        const float* src = baseQ + (size_t)(q0 + r) * HD + c0;
        __nv_bfloat16* dh = (__nv_bfloat16*)(smem + AT_QH) + r * 40 + c0;
        __nv_bfloat16* dl = (__nv_bfloat16*)(smem + AT_QL) + r * 40 + c0;
        float buf[8];
        #pragma unroll
        for (int i = 0; i < 16; i += 8) {
            *(float4*)&buf[0] = *(const float4*)(src + i);
            *(float4*)&buf[4] = *(const float4*)(src + i + 4);
            stage8(buf, dh + i, dl + i);
        }
    }
    // --- stage K (all 256 rows) ---
    {
        const float* src = baseK + (size_t)tid * HD;
        __nv_bfloat16* dh = (__nv_bfloat16*)(smem + AT_KH) + tid * 40;
        __nv_bfloat16* dl = (__nv_bfloat16*)(smem + AT_KL) + tid * 40;
        float buf[8];
        #pragma unroll
        for (int i = 0; i < 32; i += 8) {
            *(float4*)&buf[0] = *(const float4*)(src + i);
            *(float4*)&buf[4] = *(const float4*)(src + i + 4);
            stage8(buf, dh + i, dl + i);
        }
    }
    // --- stage V transposed: thread owns key k=tid, scatters d ---
    {
        const float* src = baseV + (size_t)tid * HD;
        __nv_bfloat16* vh = (__nv_bfloat16*)(smem + AT_VH);
        __nv_bfloat16* vl = (__nv_bfloat16*)(smem + AT_VL);
        #pragma unroll
        for (int d = 0; d < 32; d++) {
            float x = src[d];
            __nv_bfloat16 xh = __float2bfloat16(x);
            __nv_bfloat16 xl = __float2bfloat16(x - __bfloat162float(xh));
            vh[d * 264 + tid] = xh;
            vl[d * 264 + tid] = xl;
        }
    }
    __syncthreads();

    const uint32_t sb = smem_u32(smem);
    const int lt = lane >> 3, lr = lane & 7;
    const uint32_t aq_off  = ((w * 16 + ((lt & 1) ? 8 : 0) + lr) * 40 + ((lt & 2) ? 8 : 0)) * 2;
    const uint32_t bk_off  = ((((lt & 2) ? 8 : 0) + lr) * 40  + ((lt & 1) ? 8 : 0)) * 2;
    const uint32_t bv_off  = ((((lt & 2) ? 8 : 0) + lr) * 264 + ((lt & 1) ? 8 : 0)) * 2;

    // Q fragments (hi/lo, 2 k-steps over d)
    uint32_t aQh[2][4], aQl[2][4];
    #pragma unroll
    for (int kd = 0; kd < 2; kd++) {
        ldsm_x4(aQh[kd], sb + AT_QH + aq_off + kd * 32);
        ldsm_x4(aQl[kd], sb + AT_QL + aq_off + kd * 32);
    }

    const int qlo = q0 + w * 16 + (lane >> 2);
    const int qhi = qlo + 8;
    const float* mrow  = mb + (size_t)n * NN;
    const float* trow0 = tb + ((size_t)h * NN + qlo) * NN;
    const float* trow1 = tb + ((size_t)h * NN + qhi) * NN;

    float oacc[4][4];
    #pragma unroll
    for (int f = 0; f < 4; f++)
        #pragma unroll
        for (int i = 0; i < 4; i++) oacc[f][i] = 0.f;
    float m0 = -1e30f, m1 = -1e30f, sum0 = 0.f, sum1 = 0.f;

    #pragma unroll 1
    for (int c = 0; c < 4; c++) {
        const int kc0 = c * 64;
        float sacc[8][4];
        #pragma unroll
        for (int f = 0; f < 8; f++)
            #pragma unroll
            for (int i = 0; i < 4; i++) sacc[f][i] = 0.f;

        // S = Q K^T (3-split)
        #pragma unroll
        for (int kd = 0; kd < 2; kd++) {
            #pragma unroll
            for (int ng = 0; ng < 4; ng++) {
                uint32_t ba = sb + AT_KH + bk_off + (uint32_t)(kc0 + ng * 16) * 80 + kd * 32;
                uint32_t bh[4], bl[4];
                ldsm_x4(bh, ba);
                ldsm_x4(bl, ba + (AT_KL - AT_KH));
                mma_bf16(sacc[2*ng],   aQh[kd], bh); mma_bf16(sacc[2*ng+1], aQh[kd], bh+2);
                mma_bf16(sacc[2*ng],   aQh[kd], bl); mma_bf16(sacc[2*ng+1], aQh[kd], bl+2);
                mma_bf16(sacc[2*ng],   aQl[kd], bh); mma_bf16(sacc[2*ng+1], aQl[kd], bh+2);
            }
        }

        // bias + chunk max
        float cm0 = -1e30f, cm1 = -1e30f;
        #pragma unroll
        for (int f = 0; f < 8; f++) {
            int kcol = kc0 + f * 8 + 2 * (lane & 3);
            float2 mv = *(const float2*)(mrow  + kcol);
            float2 t0 = *(const float2*)(trow0 + kcol);
            float2 t1 = *(const float2*)(trow1 + kcol);
            sacc[f][0] += mv.x + t0.x; sacc[f][1] += mv.y + t0.y;
            sacc[f][2] += mv.x + t1.x; sacc[f][3] += mv.y + t1.y;
            cm0 = fmaxf(cm0, fmaxf(sacc[f][0], sacc[f][1]));
            cm1 = fmaxf(cm1, fmaxf(sacc[f][2], sacc[f][3]));
        }
        cm0 = fmaxf(cm0, __shfl_xor_sync(0xffffffffu, cm0, 1));
        cm0 = fmaxf(cm0, __shfl_xor_sync(0xffffffffu, cm0, 2));
        cm1 = fmaxf(cm1, __shfl_xor_sync(0xffffffffu, cm1, 1));
        cm1 = fmaxf(cm1, __shfl_xor_sync(0xffffffffu, cm1, 2));

        float mn0 = fmaxf(m0, cm0), mn1 = fmaxf(m1, cm1);
        float al0 = __expf(m0 - mn0), al1 = __expf(m1 - mn1);
        m0 = mn0; m1 = mn1;
        sum0 *= al0; sum1 *= al1;
        #pragma unroll
        for (int f = 0; f < 4; f++) {
            oacc[f][0] *= al0; oacc[f][1] *= al0;
            oacc[f][2] *= al1; oacc[f][3] *= al1;
        }
        // P = exp(S - m)
        #pragma unroll
        for (int f = 0; f < 8; f++) {
            sacc[f][0] = __expf(sacc[f][0] - mn0);
            sacc[f][1] = __expf(sacc[f][1] - mn0);
            sacc[f][2] = __expf(sacc[f][2] - mn1);
            sacc[f][3] = __expf(sacc[f][3] - mn1);
            sum0 += sacc[f][0] + sacc[f][1];
            sum1 += sacc[f][2] + sacc[f][3];
        }
        // O += P V (3-split); P fragments built by register repack
        #pragma unroll
        for (int kf = 0; kf < 4; kf++) {
            uint32_t ph[4], pl[4];
            split2(sacc[2*kf][0],   sacc[2*kf][1],   ph[0], pl[0]);
            split2(sacc[2*kf][2],   sacc[2*kf][3],   ph[1], pl[1]);
            split2(sacc[2*kf+1][0], sacc[2*kf+1][1], ph[2], pl[2]);
            split2(sacc[2*kf+1][2], sacc[2*kf+1][3], ph[3], pl[3]);
            uint32_t kbyte = (uint32_t)(kc0 + kf * 16) * 2;
            #pragma unroll
            for (int ngd = 0; ngd < 2; ngd++) {
                uint32_t bh[4], bl[4];
                uint32_t ba = sb + AT_VH + bv_off + ngd * 16 * 528 + kbyte;
                ldsm_x4(bh, ba);
                ldsm_x4(bl, ba + (AT_VL - AT_VH));
                mma_bf16(oacc[2*ngd],   ph, bh); mma_bf16(oacc[2*ngd+1], ph, bh+2);
                mma_bf16(oacc[2*ngd],   ph, bl); mma_bf16(oacc[2*ngd+1], ph, bl+2);
                mma_bf16(oacc[2*ngd],   pl, bh); mma_bf16(oacc[2*ngd+1], pl, bh+2);
            }
        }
    }

    sum0 += __shfl_xor_sync(0xffffffffu, sum0, 1);
    sum0 += __shfl_xor_sync(0xffffffffu, sum0, 2);
    sum1 += __shfl_xor_sync(0xffffffffu, sum1, 1);
    sum1 += __shfl_xor_sync(0xffffffffu, sum1, 2);
    float inv0 = 1.f / sum0, inv1 = 1.f / sum1;

    const int rid_lo = n * NN + qlo, rid_hi = n * NN + qhi;
    #pragma unroll
    for (int f = 0; f < 4; f++) {
        int d = f * 8 + 2 * (lane & 3);
        float2 glo = *(const float2*)(g_G + (size_t)rid_lo * NE + h * HD + d);
        float2 ghi = *(const float2*)(g_G + (size_t)rid_hi * NE + h * HD + d);
        float2 o0 = {oacc[f][0] * inv0 * glo.x, oacc[f][1] * inv0 * glo.y};
        float2 o1 = {oacc[f][2] * inv1 * ghi.x, oacc[f][3] * inv1 * ghi.y};
        *(float2*)(g_O + (size_t)rid_lo * NE + h * HD + d) = o0;
        *(float2*)(g_O + (size_t)rid_hi * NE + h * HD + d) = o1;
    }
}

// ---------------------------------------------------------------------------
// Kernel 3: output projection. grid=512, block=256.
// ---------------------------------------------------------------------------
#define OP_XH 0
#define OP_XL 34816
#define OP_WH 69632
#define OP_WL 104448
#define OP_SMEM 139264

__global__ __launch_bounds__(256) void mma_out_kernel(
    const float* __restrict__ bo, float* __restrict__ out)
{
    extern __shared__ __align__(16) char smem[];
    const int tid = threadIdx.x, w = tid >> 5, lane = tid & 31;
    const int r0 = blockIdx.x * 128;

    {
        int r = tid >> 1, c0 = (tid & 1) * 64;
        const float* src = g_O + (size_t)(r0 + r) * NE + c0;
        __nv_bfloat16* dh = (__nv_bfloat16*)(smem + OP_XH) + r * 136 + c0;
        __nv_bfloat16* dl = (__nv_bfloat16*)(smem + OP_XL) + r * 136 + c0;
        float buf[8];
        #pragma unroll
        for (int i = 0; i < 64; i += 8) {
            *(float4*)&buf[0] = *(const float4*)(src + i);
            *(float4*)&buf[4] = *(const float4*)(src + i + 4);
            stage8(buf, dh + i, dl + i);
        }
    }
    {
        const uint4* sh = (const uint4*)g_Wh[4];
        const uint4* sl = (const uint4*)g_Wl[4];
        uint4* dh = (uint4*)(smem + OP_WH);
        uint4* dl = (uint4*)(smem + OP_WL);
        for (int i = tid; i < 2176; i += 256) { dh[i] = sh[i]; dl[i] = sl[i]; }
    }
    __syncthreads();

    const uint32_t sb = smem_u32(smem);
    const int lt = lane >> 3, lr = lane & 7;
    const uint32_t a_off = ((w * 16 + ((lt & 1) ? 8 : 0) + lr) * 136 + ((lt & 2) ? 8 : 0)) * 2;
    const uint32_t b_off = ((((lt & 2) ? 8 : 0) + lr) * 136 + ((lt & 1) ? 8 : 0)) * 2;

    float acc[16][4];
    #pragma unroll
    for (int f = 0; f < 16; f++)
        #pragma unroll
        for (int i = 0; i < 4; i++) acc[f][i] = 0.f;

    #pragma unroll
    for (int s = 0; s < 3; s++) {
        uint32_t Ab = sb + ((s == 2) ? OP_XL : OP_XH) + a_off;
        uint32_t Bb = sb + ((s == 1) ? OP_WL : OP_WH) + b_off;
        #pragma unroll
        for (int k = 0; k < 8; k++) {
            uint32_t a[4];
            ldsm_x4(a, Ab + k * 32);
            #pragma unroll
            for (int ng = 0; ng < 8; ng++) {
                uint32_t b[4];
                ldsm_x4(b, Bb + ng * 16 * 272 + k * 32);
                mma_bf16(acc[2 * ng],     a, b);
                mma_bf16(acc[2 * ng + 1], a, b + 2);
            }
        }
    }

    const int rid_lo = r0 + w * 16 + (lane >> 2);
    const int rid_hi = rid_lo + 8;
    #pragma unroll
    for (int f = 0; f < 16; f++) {
        int cc = f * 8 + 2 * (lane & 3);
        float b0 = bo[cc], b1 = bo[cc + 1];
        *(float2*)(out + (size_t)rid_lo * CIN + cc) = make_float2(acc[f][0] + b0, acc[f][1] + b1);
        *(float2*)(out + (size_t)rid_hi * CIN + cc) = make_float2(acc[f][2] + b0, acc[f][3] + b1);
    }
}

// ---------------------------------------------------------------------------
extern "C" void kernel_launch(void* const* d_in, const int* in_sizes, int n_in,
                              void* d_out, int out_size)
{
    const float* qx  = (const float*)d_in[0];
    const float* kvx = (const float*)d_in[1];
    const float* mb  = (const float*)d_in[2];
    const float* tb  = (const float*)d_in[3];
    const float* wq  = (const float*)d_in[4];
    const float* wk  = (const float*)d_in[5];
    const float* wv  = (const float*)d_in[6];
    const float* wg  = (const float*)d_in[7];
    const float* bg  = (const float*)d_in[8];
    const float* wo  = (const float*)d_in[9];
    const float* bo  = (const float*)d_in[10];
    float* out = (float*)d_out;

    cudaFuncSetAttribute(mma_proj_kernel, cudaFuncAttributeMaxDynamicSharedMemorySize, PJ_SMEM);
    cudaFuncSetAttribute(mma_attn_kernel, cudaFuncAttributeMaxDynamicSharedMemorySize, AT_SMEM);
    cudaFuncSetAttribute(mma_out_kernel,  cudaFuncAttributeMaxDynamicSharedMemorySize, OP_SMEM);

    convw_kernel<<<5, 256>>>(wq, wk, wv, wg, wo);
    mma_proj_kernel<<<512, 256, PJ_SMEM>>>(qx, kvx, bg);
    mma_attn_kernel<<<dim3(2, NH, NN), 256, AT_SMEM>>>(mb, tb);
    mma_out_kernel<<<512, 256, OP_SMEM>>>(bo, out);
}

// round 5
// speedup vs baseline: 2.3407x; 1.1763x over previous
#include <cuda_runtime.h>
#include <cuda_bf16.h>
#include <cstdint>
#include <math.h>

#define NN  256
#define CIN 128
#define NH  4
#define HD  32
#define NE  128

// Scratch (allocation-free rule)
__device__ float g_Q[NN*NH*NN*HD];   // [n][h][q][d], pre-scaled
__device__ float g_K[NN*NH*NN*HD];   // [n][h][k][d]
__device__ float g_V[NN*NH*NN*HD];   // [n][h][k][d]
__device__ float g_G[NN*NN*NE];      // sigmoid gate [rid][e]
__device__ float g_O[NN*NN*NE];      // gated attention out [rid][e]
__device__ __align__(16) __nv_bfloat16 g_Wh[5][128][136];  // wq,wk,wv,wg,wo hi
__device__ __align__(16) __nv_bfloat16 g_Wl[5][128][136];  // lo

// ---------------------------------------------------------------------------
// helpers
// ---------------------------------------------------------------------------
__device__ __forceinline__ uint32_t smem_u32(const void* p) {
    uint32_t a;
    asm("{ .reg .u64 t; cvta.to.shared.u64 t, %1; cvt.u32.u64 %0, t; }"
        : "=r"(a) : "l"(p));
    return a;
}

__device__ __forceinline__ void ldsm_x4(uint32_t* r, uint32_t addr) {
    asm volatile("ldmatrix.sync.aligned.m8n8.x4.shared.b16 {%0,%1,%2,%3}, [%4];"
        : "=r"(r[0]), "=r"(r[1]), "=r"(r[2]), "=r"(r[3]) : "r"(addr));
}

__device__ __forceinline__ void mma_bf16(float* d, const uint32_t* a, const uint32_t* b) {
    asm volatile(
        "mma.sync.aligned.m16n8k16.row.col.f32.bf16.bf16.f32 "
        "{%0,%1,%2,%3}, {%4,%5,%6,%7}, {%8,%9}, {%0,%1,%2,%3};"
        : "+f"(d[0]), "+f"(d[1]), "+f"(d[2]), "+f"(d[3])
        : "r"(a[0]), "r"(a[1]), "r"(a[2]), "r"(a[3]), "r"(b[0]), "r"(b[1]));
}

// split two fp32 into packed bf16 hi-word and lo-word (elem0 in low half)
__device__ __forceinline__ void split2(float a, float b, uint32_t& h, uint32_t& l) {
    __nv_bfloat16 ha = __float2bfloat16(a), hb = __float2bfloat16(b);
    float la = a - __bfloat162float(ha), lb = b - __bfloat162float(hb);
    __nv_bfloat16 lA = __float2bfloat16(la), lB = __float2bfloat16(lb);
    h = (uint32_t)__bfloat16_as_ushort(ha) | ((uint32_t)__bfloat16_as_ushort(hb) << 16);
    l = (uint32_t)__bfloat16_as_ushort(lA) | ((uint32_t)__bfloat16_as_ushort(lB) << 16);
}

// convert 8 consecutive floats -> uint4 hi + uint4 lo
__device__ __forceinline__ void stage8(const float* s, void* dh, void* dl) {
    uint32_t h[4], l[4];
    #pragma unroll
    for (int p = 0; p < 4; p++) split2(s[2*p], s[2*p+1], h[p], l[p]);
    *(uint4*)dh = make_uint4(h[0], h[1], h[2], h[3]);
    *(uint4*)dl = make_uint4(l[0], l[1], l[2], l[3]);
}

// ---------------------------------------------------------------------------
// Kernel 0: convert 5 weight matrices into bf16 hi/lo, padded stride 136.
// ---------------------------------------------------------------------------
__global__ __launch_bounds__(256) void convw_kernel(
    const float* __restrict__ wq, const float* __restrict__ wk,
    const float* __restrict__ wv, const float* __restrict__ wg,
    const float* __restrict__ wo)
{
    int m = blockIdx.x;
    const float* src = (m == 0) ? wq : (m == 1) ? wk : (m == 2) ? wv : (m == 3) ? wg : wo;
    for (int idx = threadIdx.x; idx < 128 * 64; idx += 256) {
        int r = idx >> 6, cp = (idx & 63) * 2;
        uint32_t h, l;
        split2(src[r * 128 + cp], src[r * 128 + cp + 1], h, l);
        *(uint32_t*)&g_Wh[m][r][cp] = h;
        *(uint32_t*)&g_Wl[m][r][cp] = l;
    }
}

// ---------------------------------------------------------------------------
// Kernel 1: fused 4 projections. grid=512 (128-row tiles), block=512 (16 warps).
// warp w: mi = w&7 (16 rows), nh = w>>3 (64 of 128 n-cols).
// smem: XQ hi/lo, XKV hi/lo, W hi/lo, each [128][136] bf16 (34816 B).
// ---------------------------------------------------------------------------
#define PJ_XQH 0
#define PJ_XQL 34816
#define PJ_XKH 69632
#define PJ_XKL 104448
#define PJ_WH  139264
#define PJ_WL  174080
#define PJ_SMEM 208896

__global__ __launch_bounds__(512) void mma_proj_kernel(
    const float* __restrict__ qx, const float* __restrict__ kvx,
    const float* __restrict__ bg)
{
    extern __shared__ __align__(16) char smem[];
    const int tid = threadIdx.x, w = tid >> 5, lane = tid & 31;
    const int mi = w & 7, nh = w >> 3;
    const int r0 = blockIdx.x * 128;

    // stage X tiles: thread -> (row = tid/4, 32 cols)
    {
        int r = tid >> 2, c0 = (tid & 3) * 32;
        const float* xq = qx  + (size_t)(r0 + r) * CIN + c0;
        const float* xk = kvx + (size_t)(r0 + r) * CIN + c0;
        __nv_bfloat16* qh = (__nv_bfloat16*)(smem + PJ_XQH) + r * 136 + c0;
        __nv_bfloat16* ql = (__nv_bfloat16*)(smem + PJ_XQL) + r * 136 + c0;
        __nv_bfloat16* kh = (__nv_bfloat16*)(smem + PJ_XKH) + r * 136 + c0;
        __nv_bfloat16* kl = (__nv_bfloat16*)(smem + PJ_XKL) + r * 136 + c0;
        float buf[8];
        #pragma unroll
        for (int i = 0; i < 32; i += 8) {
            *(float4*)&buf[0] = *(const float4*)(xq + i);
            *(float4*)&buf[4] = *(const float4*)(xq + i + 4);
            stage8(buf, qh + i, ql + i);
            *(float4*)&buf[0] = *(const float4*)(xk + i);
            *(float4*)&buf[4] = *(const float4*)(xk + i + 4);
            stage8(buf, kh + i, kl + i);
        }
    }

    const uint32_t sb = smem_u32(smem);
    const int lt = lane >> 3, lr = lane & 7;
    const uint32_t a_off = ((uint32_t)(mi * 16 + ((lt & 1) ? 8 : 0) + lr) * 136
                           + ((lt & 2) ? 8 : 0)) * 2;
    const uint32_t b_off = ((uint32_t)(((lt & 2) ? 8 : 0) + lr) * 136
                           + ((lt & 1) ? 8 : 0)) * 2 + (uint32_t)nh * 17408;
    const float SCALE = 0.17677669529663687f;

    for (int mode = 0; mode < 4; mode++) {
        __syncthreads();
        {
            const uint4* sh = (const uint4*)g_Wh[mode];
            const uint4* sl = (const uint4*)g_Wl[mode];
            uint4* dh = (uint4*)(smem + PJ_WH);
            uint4* dl = (uint4*)(smem + PJ_WL);
            for (int i = tid; i < 2176; i += 512) { dh[i] = sh[i]; dl[i] = sl[i]; }
        }
        __syncthreads();

        const uint32_t Xh = sb + ((mode == 0 || mode == 3) ? PJ_XQH : PJ_XKH);

        float acc[8][4];
        #pragma unroll
        for (int f = 0; f < 8; f++)
            #pragma unroll
            for (int i = 0; i < 4; i++) acc[f][i] = 0.f;

        #pragma unroll
        for (int k = 0; k < 8; k++) {
            uint32_t ah[4], al[4];
            ldsm_x4(ah, Xh + a_off + k * 32);
            ldsm_x4(al, Xh + 34816 + a_off + k * 32);
            #pragma unroll
            for (int ng = 0; ng < 4; ng++) {
                uint32_t bh[4], bl[4];
                uint32_t ba = sb + PJ_WH + b_off + ng * 4352 + k * 32;
                ldsm_x4(bh, ba);
                ldsm_x4(bl, ba + (PJ_WL - PJ_WH));
                mma_bf16(acc[2*ng],   ah, bh); mma_bf16(acc[2*ng+1], ah, bh+2);
                mma_bf16(acc[2*ng],   ah, bl); mma_bf16(acc[2*ng+1], ah, bl+2);
                mma_bf16(acc[2*ng],   al, bh); mma_bf16(acc[2*ng+1], al, bh+2);
            }
        }

        // epilogue
        const int rid_lo = r0 + mi * 16 + (lane >> 2);
        const int rid_hi = rid_lo + 8;
        const int n_lo = rid_lo >> 8, q_lo = rid_lo & 255;
        const int n_hi = rid_hi >> 8, q_hi = rid_hi & 255;

        if (mode < 3) {
            float sc = (mode == 0) ? SCALE : 1.f;
            float* dstb = (mode == 0) ? g_Q : (mode == 1) ? g_K : g_V;
            #pragma unroll
            for (int f = 0; f < 8; f++) {
                int j = nh * 64 + f * 8 + 2 * (lane & 3);
                int hh = j >> 5, d = j & 31;
                float2 v0 = {acc[f][0] * sc, acc[f][1] * sc};
                float2 v1 = {acc[f][2] * sc, acc[f][3] * sc};
                *(float2*)(dstb + ((size_t)(n_lo * NH + hh) * NN + q_lo) * HD + d) = v0;
                *(float2*)(dstb + ((size_t)(n_hi * NH + hh) * NN + q_hi) * HD + d) = v1;
            }
        } else {
            #pragma unroll
            for (int f = 0; f < 8; f++) {
                int j = nh * 64 + f * 8 + 2 * (lane & 3);
                float b0 = bg[j], b1 = bg[j + 1];
                float2 v0 = {1.f / (1.f + __expf(-(acc[f][0] + b0))),
                             1.f / (1.f + __expf(-(acc[f][1] + b1)))};
                float2 v1 = {1.f / (1.f + __expf(-(acc[f][2] + b0))),
                             1.f / (1.f + __expf(-(acc[f][3] + b1)))};
                *(float2*)(g_G + (size_t)rid_lo * NE + j) = v0;
                *(float2*)(g_G + (size_t)rid_hi * NE + j) = v1;
            }
        }
    }
}

// ---------------------------------------------------------------------------
// Kernel 2: attention, FA2-style. grid=(2, NH, NN), block=256 (8 warps x 16 q).
// smem: Q hi/lo [128][40], K hi/lo [256][40], V^T hi/lo [32][264].
// ---------------------------------------------------------------------------
#define AT_QH 0
#define AT_QL 10240
#define AT_KH 20480
#define AT_KL 40960
#define AT_VH 61440
#define AT_VL 78336
#define AT_SMEM 95232

__global__ __launch_bounds__(256, 2) void mma_attn_kernel(
    const float* __restrict__ mb, const float* __restrict__ tb)
{
    extern __shared__ __align__(16) char smem[];
    const int tid = threadIdx.x, w = tid >> 5, lane = tid & 31;
    const int q0 = blockIdx.x * 128;
    const int h  = blockIdx.y;
    const int n  = blockIdx.z;

    const float* baseQ = g_Q + (size_t)(n * NH + h) * NN * HD;
    const float* baseK = g_K + (size_t)(n * NH + h) * NN * HD;
    const float* baseV = g_V + (size_t)(n * NH + h) * NN * HD;

    // --- stage Q (rows q0..q0+127) ---
    {
        int r = tid >> 1, c0 = (tid & 1) * 16;
        const float* src = baseQ + (size_t)(q0 + r) * HD + c0;
        __nv_bfloat16* dh = (__nv_bfloat16*)(smem + AT_QH) + r * 40 + c0;
        __nv_bfloat16* dl = (__nv_bfloat16*)(smem + AT_QL) + r * 40 + c0;
        float buf[8];
        #pragma unroll
        for (int i = 0; i < 16; i += 8) {
            *(float4*)&buf[0] = *(const float4*)(src + i);
            *(float4*)&buf[4] = *(const float4*)(src + i + 4);
            stage8(buf, dh + i, dl + i);
        }
    }
    // --- stage K (all 256 rows) ---
    {
        const float* src = baseK + (size_t)tid * HD;
        __nv_bfloat16* dh = (__nv_bfloat16*)(smem + AT_KH) + tid * 40;
        __nv_bfloat16* dl = (__nv_bfloat16*)(smem + AT_KL) + tid * 40;
        float buf[8];
        #pragma unroll
        for (int i = 0; i < 32; i += 8) {
            *(float4*)&buf[0] = *(const float4*)(src + i);
            *(float4*)&buf[4] = *(const float4*)(src + i + 4);
            stage8(buf, dh + i, dl + i);
        }
    }
    // --- stage V transposed ---
    {
        const float* src = baseV + (size_t)tid * HD;
        __nv_bfloat16* vh = (__nv_bfloat16*)(smem + AT_VH);
        __nv_bfloat16* vl = (__nv_bfloat16*)(smem + AT_VL);
        #pragma unroll
        for (int d = 0; d < 32; d++) {
            float x = src[d];
            __nv_bfloat16 xh = __float2bfloat16(x);
            __nv_bfloat16 xl = __float2bfloat16(x - __bfloat162float(xh));
            vh[d * 264 + tid] = xh;
            vl[d * 264 + tid] = xl;
        }
    }
    __syncthreads();

    const uint32_t sb = smem_u32(smem);
    const int lt = lane >> 3, lr = lane & 7;
    const uint32_t aq_off  = ((w * 16 + ((lt & 1) ? 8 : 0) + lr) * 40 + ((lt & 2) ? 8 : 0)) * 2;
    const uint32_t bk_off  = ((((lt & 2) ? 8 : 0) + lr) * 40  + ((lt & 1) ? 8 : 0)) * 2;
    const uint32_t bv_off  = ((((lt & 2) ? 8 : 0) + lr) * 264 + ((lt & 1) ? 8 : 0)) * 2;

    uint32_t aQh[2][4], aQl[2][4];
    #pragma unroll
    for (int kd = 0; kd < 2; kd++) {
        ldsm_x4(aQh[kd], sb + AT_QH + aq_off + kd * 32);
        ldsm_x4(aQl[kd], sb + AT_QL + aq_off + kd * 32);
    }

    const int qlo = q0 + w * 16 + (lane >> 2);
    const int qhi = qlo + 8;
    const float* mrow  = mb + (size_t)n * NN;
    const float* trow0 = tb + ((size_t)h * NN + qlo) * NN;
    const float* trow1 = tb + ((size_t)h * NN + qhi) * NN;

    float oacc[4][4];
    #pragma unroll
    for (int f = 0; f < 4; f++)
        #pragma unroll
        for (int i = 0; i < 4; i++) oacc[f][i] = 0.f;
    float m0 = -1e30f, m1 = -1e30f, sum0 = 0.f, sum1 = 0.f;

    #pragma unroll 1
    for (int c = 0; c < 4; c++) {
        const int kc0 = c * 64;
        float sacc[8][4];
        #pragma unroll
        for (int f = 0; f < 8; f++)
            #pragma unroll
            for (int i = 0; i < 4; i++) sacc[f][i] = 0.f;

        #pragma unroll
        for (int kd = 0; kd < 2; kd++) {
            #pragma unroll
            for (int ng = 0; ng < 4; ng++) {
                uint32_t ba = sb + AT_KH + bk_off + (uint32_t)(kc0 + ng * 16) * 80 + kd * 32;
                uint32_t bh[4], bl[4];
                ldsm_x4(bh, ba);
                ldsm_x4(bl, ba + (AT_KL - AT_KH));
                mma_bf16(sacc[2*ng],   aQh[kd], bh); mma_bf16(sacc[2*ng+1], aQh[kd], bh+2);
                mma_bf16(sacc[2*ng],   aQh[kd], bl); mma_bf16(sacc[2*ng+1], aQh[kd], bl+2);
                mma_bf16(sacc[2*ng],   aQl[kd], bh); mma_bf16(sacc[2*ng+1], aQl[kd], bh+2);
            }
        }

        float cm0 = -1e30f, cm1 = -1e30f;
        #pragma unroll
        for (int f = 0; f < 8; f++) {
            int kcol = kc0 + f * 8 + 2 * (lane & 3);
            float2 mv = *(const float2*)(mrow  + kcol);
            float2 t0 = *(const float2*)(trow0 + kcol);
            float2 t1 = *(const float2*)(trow1 + kcol);
            sacc[f][0] += mv.x + t0.x; sacc[f][1] += mv.y + t0.y;
            sacc[f][2] += mv.x + t1.x; sacc[f][3] += mv.y + t1.y;
            cm0 = fmaxf(cm0, fmaxf(sacc[f][0], sacc[f][1]));
            cm1 = fmaxf(cm1, fmaxf(sacc[f][2], sacc[f][3]));
        }
        cm0 = fmaxf(cm0, __shfl_xor_sync(0xffffffffu, cm0, 1));
        cm0 = fmaxf(cm0, __shfl_xor_sync(0xffffffffu, cm0, 2));
        cm1 = fmaxf(cm1, __shfl_xor_sync(0xffffffffu, cm1, 1));
        cm1 = fmaxf(cm1, __shfl_xor_sync(0xffffffffu, cm1, 2));

        float mn0 = fmaxf(m0, cm0), mn1 = fmaxf(m1, cm1);
        float al0 = __expf(m0 - mn0), al1 = __expf(m1 - mn1);
        m0 = mn0; m1 = mn1;
        sum0 *= al0; sum1 *= al1;
        #pragma unroll
        for (int f = 0; f < 4; f++) {
            oacc[f][0] *= al0; oacc[f][1] *= al0;
            oacc[f][2] *= al1; oacc[f][3] *= al1;
        }
        #pragma unroll
        for (int f = 0; f < 8; f++) {
            sacc[f][0] = __expf(sacc[f][0] - mn0);
            sacc[f][1] = __expf(sacc[f][1] - mn0);
            sacc[f][2] = __expf(sacc[f][2] - mn1);
            sacc[f][3] = __expf(sacc[f][3] - mn1);
            sum0 += sacc[f][0] + sacc[f][1];
            sum1 += sacc[f][2] + sacc[f][3];
        }
        #pragma unroll
        for (int kf = 0; kf < 4; kf++) {
            uint32_t ph[4], pl[4];
            split2(sacc[2*kf][0],   sacc[2*kf][1],   ph[0], pl[0]);
            split2(sacc[2*kf][2],   sacc[2*kf][3],   ph[1], pl[1]);
            split2(sacc[2*kf+1][0], sacc[2*kf+1][1], ph[2], pl[2]);
            split2(sacc[2*kf+1][2], sacc[2*kf+1][3], ph[3], pl[3]);
            uint32_t kbyte = (uint32_t)(kc0 + kf * 16) * 2;
            #pragma unroll
            for (int ngd = 0; ngd < 2; ngd++) {
                uint32_t bh[4], bl[4];
                uint32_t ba = sb + AT_VH + bv_off + ngd * 16 * 528 + kbyte;
                ldsm_x4(bh, ba);
                ldsm_x4(bl, ba + (AT_VL - AT_VH));
                mma_bf16(oacc[2*ngd],   ph, bh); mma_bf16(oacc[2*ngd+1], ph, bh+2);
                mma_bf16(oacc[2*ngd],   ph, bl); mma_bf16(oacc[2*ngd+1], ph, bl+2);
                mma_bf16(oacc[2*ngd],   pl, bh); mma_bf16(oacc[2*ngd+1], pl, bh+2);
            }
        }
    }

    sum0 += __shfl_xor_sync(0xffffffffu, sum0, 1);
    sum0 += __shfl_xor_sync(0xffffffffu, sum0, 2);
    sum1 += __shfl_xor_sync(0xffffffffu, sum1, 1);
    sum1 += __shfl_xor_sync(0xffffffffu, sum1, 2);
    float inv0 = 1.f / sum0, inv1 = 1.f / sum1;

    const int rid_lo = n * NN + qlo, rid_hi = n * NN + qhi;
    #pragma unroll
    for (int f = 0; f < 4; f++) {
        int d = f * 8 + 2 * (lane & 3);
        float2 glo = *(const float2*)(g_G + (size_t)rid_lo * NE + h * HD + d);
        float2 ghi = *(const float2*)(g_G + (size_t)rid_hi * NE + h * HD + d);
        float2 o0 = {oacc[f][0] * inv0 * glo.x, oacc[f][1] * inv0 * glo.y};
        float2 o1 = {oacc[f][2] * inv1 * ghi.x, oacc[f][3] * inv1 * ghi.y};
        *(float2*)(g_O + (size_t)rid_lo * NE + h * HD + d) = o0;
        *(float2*)(g_O + (size_t)rid_hi * NE + h * HD + d) = o1;
    }
}

// ---------------------------------------------------------------------------
// Kernel 3: output projection. grid=512, block=512 (16 warps, N-split).
// ---------------------------------------------------------------------------
#define OP_XH 0
#define OP_XL 34816
#define OP_WH 69632
#define OP_WL 104448
#define OP_SMEM 139264

__global__ __launch_bounds__(512) void mma_out_kernel(
    const float* __restrict__ bo, float* __restrict__ out)
{
    extern __shared__ __align__(16) char smem[];
    const int tid = threadIdx.x, w = tid >> 5, lane = tid & 31;
    const int mi = w & 7, nh = w >> 3;
    const int r0 = blockIdx.x * 128;

    {
        int r = tid >> 2, c0 = (tid & 3) * 32;
        const float* src = g_O + (size_t)(r0 + r) * NE + c0;
        __nv_bfloat16* dh = (__nv_bfloat16*)(smem + OP_XH) + r * 136 + c0;
        __nv_bfloat16* dl = (__nv_bfloat16*)(smem + OP_XL) + r * 136 + c0;
        float buf[8];
        #pragma unroll
        for (int i = 0; i < 32; i += 8) {
            *(float4*)&buf[0] = *(const float4*)(src + i);
            *(float4*)&buf[4] = *(const float4*)(src + i + 4);
            stage8(buf, dh + i, dl + i);
        }
    }
    {
        const uint4* sh = (const uint4*)g_Wh[4];
        const uint4* sl = (const uint4*)g_Wl[4];
        uint4* dh = (uint4*)(smem + OP_WH);
        uint4* dl = (uint4*)(smem + OP_WL);
        for (int i = tid; i < 2176; i += 512) { dh[i] = sh[i]; dl[i] = sl[i]; }
    }
    __syncthreads();

    const uint32_t sb = smem_u32(smem);
    const int lt = lane >> 3, lr = lane & 7;
    const uint32_t a_off = ((uint32_t)(mi * 16 + ((lt & 1) ? 8 : 0) + lr) * 136
                           + ((lt & 2) ? 8 : 0)) * 2;
    const uint32_t b_off = ((uint32_t)(((lt & 2) ? 8 : 0) + lr) * 136
                           + ((lt & 1) ? 8 : 0)) * 2 + (uint32_t)nh * 17408;

    float acc[8][4];
    #pragma unroll
    for (int f = 0; f < 8; f++)
        #pragma unroll
        for (int i = 0; i < 4; i++) acc[f][i] = 0.f;

    #pragma unroll
    for (int k = 0; k < 8; k++) {
        uint32_t ah[4], al[4];
        ldsm_x4(ah, sb + OP_XH + a_off + k * 32);
        ldsm_x4(al, sb + OP_XL + a_off + k * 32);
        #pragma unroll
        for (int ng = 0; ng < 4; ng++) {
            uint32_t bh[4], bl[4];
            uint32_t ba = sb + OP_WH + b_off + ng * 4352 + k * 32;
            ldsm_x4(bh, ba);
            ldsm_x4(bl, ba + (OP_WL - OP_WH));
            mma_bf16(acc[2*ng],   ah, bh); mma_bf16(acc[2*ng+1], ah, bh+2);
            mma_bf16(acc[2*ng],   ah, bl); mma_bf16(acc[2*ng+1], ah, bl+2);
            mma_bf16(acc[2*ng],   al, bh); mma_bf16(acc[2*ng+1], al, bh+2);
        }
    }

    const int rid_lo = r0 + mi * 16 + (lane >> 2);
    const int rid_hi = rid_lo + 8;
    #pragma unroll
    for (int f = 0; f < 8; f++) {
        int cc = nh * 64 + f * 8 + 2 * (lane & 3);
        float b0 = bo[cc], b1 = bo[cc + 1];
        *(float2*)(out + (size_t)rid_lo * CIN + cc) = make_float2(acc[f][0] + b0, acc[f][1] + b1);
        *(float2*)(out + (size_t)rid_hi * CIN + cc) = make_float2(acc[f][2] + b0, acc[f][3] + b1);
    }
}

// ---------------------------------------------------------------------------
extern "C" void kernel_launch(void* const* d_in, const int* in_sizes, int n_in,
                              void* d_out, int out_size)
{
    const float* qx  = (const float*)d_in[0];
    const float* kvx = (const float*)d_in[1];
    const float* mb  = (const float*)d_in[2];
    const float* tb  = (const float*)d_in[3];
    const float* wq  = (const float*)d_in[4];
    const float* wk  = (const float*)d_in[5];
    const float* wv  = (const float*)d_in[6];
    const float* wg  = (const float*)d_in[7];
    const float* bg  = (const float*)d_in[8];
    const float* wo  = (const float*)d_in[9];
    const float* bo  = (const float*)d_in[10];
    float* out = (float*)d_out;

    cudaFuncSetAttribute(mma_proj_kernel, cudaFuncAttributeMaxDynamicSharedMemorySize, PJ_SMEM);
    cudaFuncSetAttribute(mma_attn_kernel, cudaFuncAttributeMaxDynamicSharedMemorySize, AT_SMEM);
    cudaFuncSetAttribute(mma_out_kernel,  cudaFuncAttributeMaxDynamicSharedMemorySize, OP_SMEM);

    convw_kernel<<<5, 256>>>(wq, wk, wv, wg, wo);
    mma_proj_kernel<<<512, 512, PJ_SMEM>>>(qx, kvx, bg);
    mma_attn_kernel<<<dim3(2, NH, NN), 256, AT_SMEM>>>(mb, tb);
    mma_out_kernel<<<512, 512, OP_SMEM>>>(bo, out);
}

// round 6
// speedup vs baseline: 2.4539x; 1.0484x over previous
#include <cuda_runtime.h>
#include <cuda_bf16.h>
#include <cstdint>
#include <math.h>

#define NN  256
#define CIN 128
#define NH  4
#define HD  32
#define NE  128

// Scratch (allocation-free rule)
__device__ float g_Q[NN*NH*NN*HD];   // [n][h][q][d], pre-scaled
__device__ float g_K[NN*NH*NN*HD];   // [n][h][k][d]
__device__ float g_V[NN*NH*NN*HD];   // [n][h][k][d]
__device__ float g_G[NN*NN*NE];      // sigmoid gate [rid][e]
__device__ float g_O[NN*NN*NE];      // gated attention out [rid][e]
__device__ __align__(16) __nv_bfloat16 g_Wh[5][128][136];  // wq,wk,wv,wg,wo hi
__device__ __align__(16) __nv_bfloat16 g_Wl[5][128][136];  // lo

// ---------------------------------------------------------------------------
// helpers
// ---------------------------------------------------------------------------
__device__ __forceinline__ uint32_t smem_u32(const void* p) {
    uint32_t a;
    asm("{ .reg .u64 t; cvta.to.shared.u64 t, %1; cvt.u32.u64 %0, t; }"
        : "=r"(a) : "l"(p));
    return a;
}

__device__ __forceinline__ void ldsm_x4(uint32_t* r, uint32_t addr) {
    asm volatile("ldmatrix.sync.aligned.m8n8.x4.shared.b16 {%0,%1,%2,%3}, [%4];"
        : "=r"(r[0]), "=r"(r[1]), "=r"(r[2]), "=r"(r[3]) : "r"(addr));
}

__device__ __forceinline__ void mma_bf16(float* d, const uint32_t* a, const uint32_t* b) {
    asm volatile(
        "mma.sync.aligned.m16n8k16.row.col.f32.bf16.bf16.f32 "
        "{%0,%1,%2,%3}, {%4,%5,%6,%7}, {%8,%9}, {%0,%1,%2,%3};"
        : "+f"(d[0]), "+f"(d[1]), "+f"(d[2]), "+f"(d[3])
        : "r"(a[0]), "r"(a[1]), "r"(a[2]), "r"(a[3]), "r"(b[0]), "r"(b[1]));
}

// split two fp32 into packed bf16 hi-word and lo-word (elem0 in low half)
__device__ __forceinline__ void split2(float a, float b, uint32_t& h, uint32_t& l) {
    __nv_bfloat16 ha = __float2bfloat16(a), hb = __float2bfloat16(b);
    float la = a - __bfloat162float(ha), lb = b - __bfloat162float(hb);
    __nv_bfloat16 lA = __float2bfloat16(la), lB = __float2bfloat16(lb);
    h = (uint32_t)__bfloat16_as_ushort(ha) | ((uint32_t)__bfloat16_as_ushort(hb) << 16);
    l = (uint32_t)__bfloat16_as_ushort(lA) | ((uint32_t)__bfloat16_as_ushort(lB) << 16);
}

// convert 8 consecutive floats -> uint4 hi + uint4 lo
__device__ __forceinline__ void stage8(const float* s, void* dh, void* dl) {
    uint32_t h[4], l[4];
    #pragma unroll
    for (int p = 0; p < 4; p++) split2(s[2*p], s[2*p+1], h[p], l[p]);
    *(uint4*)dh = make_uint4(h[0], h[1], h[2], h[3]);
    *(uint4*)dl = make_uint4(l[0], l[1], l[2], l[3]);
}

// convert 8 consecutive floats -> uint4 hi only
__device__ __forceinline__ void stage8h(const float* s, void* dh) {
    uint32_t h[4];
    #pragma unroll
    for (int p = 0; p < 4; p++) {
        __nv_bfloat16 a = __float2bfloat16(s[2*p]), b = __float2bfloat16(s[2*p+1]);
        h[p] = (uint32_t)__bfloat16_as_ushort(a) | ((uint32_t)__bfloat16_as_ushort(b) << 16);
    }
    *(uint4*)dh = make_uint4(h[0], h[1], h[2], h[3]);
}

// ---------------------------------------------------------------------------
// Kernel 0: convert 5 weight matrices into bf16 hi/lo, padded stride 136.
// ---------------------------------------------------------------------------
__global__ __launch_bounds__(256) void convw_kernel(
    const float* __restrict__ wq, const float* __restrict__ wk,
    const float* __restrict__ wv, const float* __restrict__ wg,
    const float* __restrict__ wo)
{
    int m = blockIdx.x;
    const float* src = (m == 0) ? wq : (m == 1) ? wk : (m == 2) ? wv : (m == 3) ? wg : wo;
    for (int idx = threadIdx.x; idx < 128 * 64; idx += 256) {
        int r = idx >> 6, cp = (idx & 63) * 2;
        uint32_t h, l;
        split2(src[r * 128 + cp], src[r * 128 + cp + 1], h, l);
        *(uint32_t*)&g_Wh[m][r][cp] = h;
        *(uint32_t*)&g_Wl[m][r][cp] = l;
    }
}

// ---------------------------------------------------------------------------
// Kernel 1: fused 4 projections. grid=512 (128-row tiles), block=512 (16 warps).
// ---------------------------------------------------------------------------
#define PJ_XQH 0
#define PJ_XQL 34816
#define PJ_XKH 69632
#define PJ_XKL 104448
#define PJ_WH  139264
#define PJ_WL  174080
#define PJ_SMEM 208896

__global__ __launch_bounds__(512) void mma_proj_kernel(
    const float* __restrict__ qx, const float* __restrict__ kvx,
    const float* __restrict__ bg)
{
    extern __shared__ __align__(16) char smem[];
    const int tid = threadIdx.x, w = tid >> 5, lane = tid & 31;
    const int mi = w & 7, nh = w >> 3;
    const int r0 = blockIdx.x * 128;

    {
        int r = tid >> 2, c0 = (tid & 3) * 32;
        const float* xq = qx  + (size_t)(r0 + r) * CIN + c0;
        const float* xk = kvx + (size_t)(r0 + r) * CIN + c0;
        __nv_bfloat16* qh = (__nv_bfloat16*)(smem + PJ_XQH) + r * 136 + c0;
        __nv_bfloat16* ql = (__nv_bfloat16*)(smem + PJ_XQL) + r * 136 + c0;
        __nv_bfloat16* kh = (__nv_bfloat16*)(smem + PJ_XKH) + r * 136 + c0;
        __nv_bfloat16* kl = (__nv_bfloat16*)(smem + PJ_XKL) + r * 136 + c0;
        float buf[8];
        #pragma unroll
        for (int i = 0; i < 32; i += 8) {
            *(float4*)&buf[0] = *(const float4*)(xq + i);
            *(float4*)&buf[4] = *(const float4*)(xq + i + 4);
            stage8(buf, qh + i, ql + i);
            *(float4*)&buf[0] = *(const float4*)(xk + i);
            *(float4*)&buf[4] = *(const float4*)(xk + i + 4);
            stage8(buf, kh + i, kl + i);
        }
    }

    const uint32_t sb = smem_u32(smem);
    const int lt = lane >> 3, lr = lane & 7;
    const uint32_t a_off = ((uint32_t)(mi * 16 + ((lt & 1) ? 8 : 0) + lr) * 136
                           + ((lt & 2) ? 8 : 0)) * 2;
    const uint32_t b_off = ((uint32_t)(((lt & 2) ? 8 : 0) + lr) * 136
                           + ((lt & 1) ? 8 : 0)) * 2 + (uint32_t)nh * 17408;
    const float SCALE = 0.17677669529663687f;

    for (int mode = 0; mode < 4; mode++) {
        __syncthreads();
        {
            const uint4* sh = (const uint4*)g_Wh[mode];
            const uint4* sl = (const uint4*)g_Wl[mode];
            uint4* dh = (uint4*)(smem + PJ_WH);
            uint4* dl = (uint4*)(smem + PJ_WL);
            for (int i = tid; i < 2176; i += 512) { dh[i] = sh[i]; dl[i] = sl[i]; }
        }
        __syncthreads();

        const uint32_t Xh = sb + ((mode == 0 || mode == 3) ? PJ_XQH : PJ_XKH);

        float acc[8][4];
        #pragma unroll
        for (int f = 0; f < 8; f++)
            #pragma unroll
            for (int i = 0; i < 4; i++) acc[f][i] = 0.f;

        #pragma unroll
        for (int k = 0; k < 8; k++) {
            uint32_t ah[4], al[4];
            ldsm_x4(ah, Xh + a_off + k * 32);
            ldsm_x4(al, Xh + 34816 + a_off + k * 32);
            #pragma unroll
            for (int ng = 0; ng < 4; ng++) {
                uint32_t bh[4], bl[4];
                uint32_t ba = sb + PJ_WH + b_off + ng * 4352 + k * 32;
                ldsm_x4(bh, ba);
                ldsm_x4(bl, ba + (PJ_WL - PJ_WH));
                mma_bf16(acc[2*ng],   ah, bh); mma_bf16(acc[2*ng+1], ah, bh+2);
                mma_bf16(acc[2*ng],   ah, bl); mma_bf16(acc[2*ng+1], ah, bl+2);
                mma_bf16(acc[2*ng],   al, bh); mma_bf16(acc[2*ng+1], al, bh+2);
            }
        }

        const int rid_lo = r0 + mi * 16 + (lane >> 2);
        const int rid_hi = rid_lo + 8;
        const int n_lo = rid_lo >> 8, q_lo = rid_lo & 255;
        const int n_hi = rid_hi >> 8, q_hi = rid_hi & 255;

        if (mode < 3) {
            float sc = (mode == 0) ? SCALE : 1.f;
            float* dstb = (mode == 0) ? g_Q : (mode == 1) ? g_K : g_V;
            #pragma unroll
            for (int f = 0; f < 8; f++) {
                int j = nh * 64 + f * 8 + 2 * (lane & 3);
                int hh = j >> 5, d = j & 31;
                float2 v0 = {acc[f][0] * sc, acc[f][1] * sc};
                float2 v1 = {acc[f][2] * sc, acc[f][3] * sc};
                *(float2*)(dstb + ((size_t)(n_lo * NH + hh) * NN + q_lo) * HD + d) = v0;
                *(float2*)(dstb + ((size_t)(n_hi * NH + hh) * NN + q_hi) * HD + d) = v1;
            }
        } else {
            #pragma unroll
            for (int f = 0; f < 8; f++) {
                int j = nh * 64 + f * 8 + 2 * (lane & 3);
                float b0 = bg[j], b1 = bg[j + 1];
                float2 v0 = {1.f / (1.f + __expf(-(acc[f][0] + b0))),
                             1.f / (1.f + __expf(-(acc[f][1] + b1)))};
                float2 v1 = {1.f / (1.f + __expf(-(acc[f][2] + b0))),
                             1.f / (1.f + __expf(-(acc[f][3] + b1)))};
                *(float2*)(g_G + (size_t)rid_lo * NE + j) = v0;
                *(float2*)(g_G + (size_t)rid_hi * NE + j) = v1;
            }
        }
    }
}

// ---------------------------------------------------------------------------
// Kernel 2: attention. grid=(2, NH, NN), block=256 (8 warps x 16 q).
// Q,K single bf16 (score abs-err ~2e-4, biases added fp32); no max-subtraction
// (scores bounded ~5; masked -1e9 underflows to 0). V/P keep hi/lo 3-split.
// smem: Q hi [128][40], K hi [256][40], V^T hi/lo [32][264]  = 63 KB -> 3 CTA/SM
// ---------------------------------------------------------------------------
#define AT_QH 0
#define AT_KH 10240
#define AT_VH 30720
#define AT_VL 47616
#define AT_SMEM 64512

__global__ __launch_bounds__(256, 3) void mma_attn_kernel(
    const float* __restrict__ mb, const float* __restrict__ tb)
{
    extern __shared__ __align__(16) char smem[];
    const int tid = threadIdx.x, w = tid >> 5, lane = tid & 31;
    const int q0 = blockIdx.x * 128;
    const int h  = blockIdx.y;
    const int n  = blockIdx.z;

    const float* baseQ = g_Q + (size_t)(n * NH + h) * NN * HD;
    const float* baseK = g_K + (size_t)(n * NH + h) * NN * HD;
    const float* baseV = g_V + (size_t)(n * NH + h) * NN * HD;

    // --- stage Q hi (rows q0..q0+127) ---
    {
        int r = tid >> 1, c0 = (tid & 1) * 16;
        const float* src = baseQ + (size_t)(q0 + r) * HD + c0;
        __nv_bfloat16* dh = (__nv_bfloat16*)(smem + AT_QH) + r * 40 + c0;
        float buf[8];
        #pragma unroll
        for (int i = 0; i < 16; i += 8) {
            *(float4*)&buf[0] = *(const float4*)(src + i);
            *(float4*)&buf[4] = *(const float4*)(src + i + 4);
            stage8h(buf, dh + i);
        }
    }
    // --- stage K hi (all 256 rows) ---
    {
        const float* src = baseK + (size_t)tid * HD;
        __nv_bfloat16* dh = (__nv_bfloat16*)(smem + AT_KH) + tid * 40;
        float buf[8];
        #pragma unroll
        for (int i = 0; i < 32; i += 8) {
            *(float4*)&buf[0] = *(const float4*)(src + i);
            *(float4*)&buf[4] = *(const float4*)(src + i + 4);
            stage8h(buf, dh + i);
        }
    }
    // --- stage V transposed hi/lo ---
    {
        const float* src = baseV + (size_t)tid * HD;
        __nv_bfloat16* vh = (__nv_bfloat16*)(smem + AT_VH);
        __nv_bfloat16* vl = (__nv_bfloat16*)(smem + AT_VL);
        #pragma unroll
        for (int d = 0; d < 32; d++) {
            float x = src[d];
            __nv_bfloat16 xh = __float2bfloat16(x);
            __nv_bfloat16 xl = __float2bfloat16(x - __bfloat162float(xh));
            vh[d * 264 + tid] = xh;
            vl[d * 264 + tid] = xl;
        }
    }
    __syncthreads();

    const uint32_t sb = smem_u32(smem);
    const int lt = lane >> 3, lr = lane & 7;
    const uint32_t aq_off  = ((w * 16 + ((lt & 1) ? 8 : 0) + lr) * 40 + ((lt & 2) ? 8 : 0)) * 2;
    const uint32_t bk_off  = ((((lt & 2) ? 8 : 0) + lr) * 40  + ((lt & 1) ? 8 : 0)) * 2;
    const uint32_t bv_off  = ((((lt & 2) ? 8 : 0) + lr) * 264 + ((lt & 1) ? 8 : 0)) * 2;

    uint32_t aQh[2][4];
    #pragma unroll
    for (int kd = 0; kd < 2; kd++)
        ldsm_x4(aQh[kd], sb + AT_QH + aq_off + kd * 32);

    const int qlo = q0 + w * 16 + (lane >> 2);
    const int qhi = qlo + 8;
    const float* mrow  = mb + (size_t)n * NN;
    const float* trow0 = tb + ((size_t)h * NN + qlo) * NN;
    const float* trow1 = tb + ((size_t)h * NN + qhi) * NN;

    float oacc[4][4];
    #pragma unroll
    for (int f = 0; f < 4; f++)
        #pragma unroll
        for (int i = 0; i < 4; i++) oacc[f][i] = 0.f;
    float sum0 = 0.f, sum1 = 0.f;

    #pragma unroll 1
    for (int c = 0; c < 4; c++) {
        const int kc0 = c * 64;
        float sacc[8][4];
        #pragma unroll
        for (int f = 0; f < 8; f++)
            #pragma unroll
            for (int i = 0; i < 4; i++) sacc[f][i] = 0.f;

        // S = Q K^T (plain bf16)
        #pragma unroll
        for (int kd = 0; kd < 2; kd++) {
            #pragma unroll
            for (int ng = 0; ng < 4; ng++) {
                uint32_t bh[4];
                ldsm_x4(bh, sb + AT_KH + bk_off + (uint32_t)(kc0 + ng * 16) * 80 + kd * 32);
                mma_bf16(sacc[2*ng],   aQh[kd], bh);
                mma_bf16(sacc[2*ng+1], aQh[kd], bh+2);
            }
        }

        // biases + exp (no max subtraction), accumulate sums
        #pragma unroll
        for (int f = 0; f < 8; f++) {
            int kcol = kc0 + f * 8 + 2 * (lane & 3);
            float2 mv = *(const float2*)(mrow  + kcol);
            float2 t0 = *(const float2*)(trow0 + kcol);
            float2 t1 = *(const float2*)(trow1 + kcol);
            sacc[f][0] = __expf(sacc[f][0] + mv.x + t0.x);
            sacc[f][1] = __expf(sacc[f][1] + mv.y + t0.y);
            sacc[f][2] = __expf(sacc[f][2] + mv.x + t1.x);
            sacc[f][3] = __expf(sacc[f][3] + mv.y + t1.y);
            sum0 += sacc[f][0] + sacc[f][1];
            sum1 += sacc[f][2] + sacc[f][3];
        }

        // O += P V (3-split: ph*vh + ph*vl + pl*vh)
        #pragma unroll
        for (int kf = 0; kf < 4; kf++) {
            uint32_t ph[4], pl[4];
            split2(sacc[2*kf][0],   sacc[2*kf][1],   ph[0], pl[0]);
            split2(sacc[2*kf][2],   sacc[2*kf][3],   ph[1], pl[1]);
            split2(sacc[2*kf+1][0], sacc[2*kf+1][1], ph[2], pl[2]);
            split2(sacc[2*kf+1][2], sacc[2*kf+1][3], ph[3], pl[3]);
            uint32_t kbyte = (uint32_t)(kc0 + kf * 16) * 2;
            #pragma unroll
            for (int ngd = 0; ngd < 2; ngd++) {
                uint32_t bh[4], bl[4];
                uint32_t ba = sb + AT_VH + bv_off + ngd * 16 * 528 + kbyte;
                ldsm_x4(bh, ba);
                ldsm_x4(bl, ba + (AT_VL - AT_VH));
                mma_bf16(oacc[2*ngd],   ph, bh); mma_bf16(oacc[2*ngd+1], ph, bh+2);
                mma_bf16(oacc[2*ngd],   ph, bl); mma_bf16(oacc[2*ngd+1], ph, bl+2);
                mma_bf16(oacc[2*ngd],   pl, bh); mma_bf16(oacc[2*ngd+1], pl, bh+2);
            }
        }
    }

    sum0 += __shfl_xor_sync(0xffffffffu, sum0, 1);
    sum0 += __shfl_xor_sync(0xffffffffu, sum0, 2);
    sum1 += __shfl_xor_sync(0xffffffffu, sum1, 1);
    sum1 += __shfl_xor_sync(0xffffffffu, sum1, 2);
    float inv0 = 1.f / sum0, inv1 = 1.f / sum1;

    const int rid_lo = n * NN + qlo, rid_hi = n * NN + qhi;
    #pragma unroll
    for (int f = 0; f < 4; f++) {
        int d = f * 8 + 2 * (lane & 3);
        float2 glo = *(const float2*)(g_G + (size_t)rid_lo * NE + h * HD + d);
        float2 ghi = *(const float2*)(g_G + (size_t)rid_hi * NE + h * HD + d);
        float2 o0 = {oacc[f][0] * inv0 * glo.x, oacc[f][1] * inv0 * glo.y};
        float2 o1 = {oacc[f][2] * inv1 * ghi.x, oacc[f][3] * inv1 * ghi.y};
        *(float2*)(g_O + (size_t)rid_lo * NE + h * HD + d) = o0;
        *(float2*)(g_O + (size_t)rid_hi * NE + h * HD + d) = o1;
    }
}

// ---------------------------------------------------------------------------
// Kernel 3: output projection. grid=512, block=512 (16 warps, N-split).
// ---------------------------------------------------------------------------
#define OP_XH 0
#define OP_XL 34816
#define OP_WH 69632
#define OP_WL 104448
#define OP_SMEM 139264

__global__ __launch_bounds__(512) void mma_out_kernel(
    const float* __restrict__ bo, float* __restrict__ out)
{
    extern __shared__ __align__(16) char smem[];
    const int tid = threadIdx.x, w = tid >> 5, lane = tid & 31;
    const int mi = w & 7, nh = w >> 3;
    const int r0 = blockIdx.x * 128;

    {
        int r = tid >> 2, c0 = (tid & 3) * 32;
        const float* src = g_O + (size_t)(r0 + r) * NE + c0;
        __nv_bfloat16* dh = (__nv_bfloat16*)(smem + OP_XH) + r * 136 + c0;
        __nv_bfloat16* dl = (__nv_bfloat16*)(smem + OP_XL) + r * 136 + c0;
        float buf[8];
        #pragma unroll
        for (int i = 0; i < 32; i += 8) {
            *(float4*)&buf[0] = *(const float4*)(src + i);
            *(float4*)&buf[4] = *(const float4*)(src + i + 4);
            stage8(buf, dh + i, dl + i);
        }
    }
    {
        const uint4* sh = (const uint4*)g_Wh[4];
        const uint4* sl = (const uint4*)g_Wl[4];
        uint4* dh = (uint4*)(smem + OP_WH);
        uint4* dl = (uint4*)(smem + OP_WL);
        for (int i = tid; i < 2176; i += 512) { dh[i] = sh[i]; dl[i] = sl[i]; }
    }
    __syncthreads();

    const uint32_t sb = smem_u32(smem);
    const int lt = lane >> 3, lr = lane & 7;
    const uint32_t a_off = ((uint32_t)(mi * 16 + ((lt & 1) ? 8 : 0) + lr) * 136
                           + ((lt & 2) ? 8 : 0)) * 2;
    const uint32_t b_off = ((uint32_t)(((lt & 2) ? 8 : 0) + lr) * 136
                           + ((lt & 1) ? 8 : 0)) * 2 + (uint32_t)nh * 17408;

    float acc[8][4];
    #pragma unroll
    for (int f = 0; f < 8; f++)
        #pragma unroll
        for (int i = 0; i < 4; i++) acc[f][i] = 0.f;

    #pragma unroll
    for (int k = 0; k < 8; k++) {
        uint32_t ah[4], al[4];
        ldsm_x4(ah, sb + OP_XH + a_off + k * 32);
        ldsm_x4(al, sb + OP_XL + a_off + k * 32);
        #pragma unroll
        for (int ng = 0; ng < 4; ng++) {
            uint32_t bh[4], bl[4];
            uint32_t ba = sb + OP_WH + b_off + ng * 4352 + k * 32;
            ldsm_x4(bh, ba);
            ldsm_x4(bl, ba + (OP_WL - OP_WH));
            mma_bf16(acc[2*ng],   ah, bh); mma_bf16(acc[2*ng+1], ah, bh+2);
            mma_bf16(acc[2*ng],   ah, bl); mma_bf16(acc[2*ng+1], ah, bl+2);
            mma_bf16(acc[2*ng],   al, bh); mma_bf16(acc[2*ng+1], al, bh+2);
        }
    }

    const int rid_lo = r0 + mi * 16 + (lane >> 2);
    const int rid_hi = rid_lo + 8;
    #pragma unroll
    for (int f = 0; f < 8; f++) {
        int cc = nh * 64 + f * 8 + 2 * (lane & 3);
        float b0 = bo[cc], b1 = bo[cc + 1];
        *(float2*)(out + (size_t)rid_lo * CIN + cc) = make_float2(acc[f][0] + b0, acc[f][1] + b1);
        *(float2*)(out + (size_t)rid_hi * CIN + cc) = make_float2(acc[f][2] + b0, acc[f][3] + b1);
    }
}

// ---------------------------------------------------------------------------
extern "C" void kernel_launch(void* const* d_in, const int* in_sizes, int n_in,
                              void* d_out, int out_size)
{
    const float* qx  = (const float*)d_in[0];
    const float* kvx = (const float*)d_in[1];
    const float* mb  = (const float*)d_in[2];
    const float* tb  = (const float*)d_in[3];
    const float* wq  = (const float*)d_in[4];
    const float* wk  = (const float*)d_in[5];
    const float* wv  = (const float*)d_in[6];
    const float* wg  = (const float*)d_in[7];
    const float* bg  = (const float*)d_in[8];
    const float* wo  = (const float*)d_in[9];
    const float* bo  = (const float*)d_in[10];
    float* out = (float*)d_out;

    cudaFuncSetAttribute(mma_proj_kernel, cudaFuncAttributeMaxDynamicSharedMemorySize, PJ_SMEM);
    cudaFuncSetAttribute(mma_attn_kernel, cudaFuncAttributeMaxDynamicSharedMemorySize, AT_SMEM);
    cudaFuncSetAttribute(mma_out_kernel,  cudaFuncAttributeMaxDynamicSharedMemorySize, OP_SMEM);

    convw_kernel<<<5, 256>>>(wq, wk, wv, wg, wo);
    mma_proj_kernel<<<512, 512, PJ_SMEM>>>(qx, kvx, bg);
    mma_attn_kernel<<<dim3(2, NH, NN), 256, AT_SMEM>>>(mb, tb);
    mma_out_kernel<<<512, 512, OP_SMEM>>>(bo, out);
}

// round 7
// speedup vs baseline: 2.6165x; 1.0663x over previous
#include <cuda_runtime.h>
#include <cuda_bf16.h>
#include <cstdint>
#include <math.h>

#define NN  256
#define CIN 128
#define NH  4
#define HD  32
#define NE  128

// Scratch (allocation-free rule)
__device__ float g_Q[NN*NH*NN*HD];   // [n][h][q][d], pre-scaled
__device__ float g_K[NN*NH*NN*HD];   // [n][h][k][d]
__device__ float g_V[NN*NH*NN*HD];   // [n][h][k][d]
__device__ float g_G[NN*NN*NE];      // sigmoid gate [rid][e]
__device__ float g_O[NN*NN*NE];      // gated attention out [rid][e]
__device__ __align__(16) __nv_bfloat16 g_Wh[5][128][136];  // wq,wk,wv,wg,wo hi
__device__ __align__(16) __nv_bfloat16 g_Wl[5][128][136];  // lo

// ---------------------------------------------------------------------------
// helpers
// ---------------------------------------------------------------------------
__device__ __forceinline__ uint32_t smem_u32(const void* p) {
    uint32_t a;
    asm("{ .reg .u64 t; cvta.to.shared.u64 t, %1; cvt.u32.u64 %0, t; }"
        : "=r"(a) : "l"(p));
    return a;
}

__device__ __forceinline__ void ldsm_x4(uint32_t* r, uint32_t addr) {
    asm volatile("ldmatrix.sync.aligned.m8n8.x4.shared.b16 {%0,%1,%2,%3}, [%4];"
        : "=r"(r[0]), "=r"(r[1]), "=r"(r[2]), "=r"(r[3]) : "r"(addr));
}

__device__ __forceinline__ void mma_bf16(float* d, const uint32_t* a, const uint32_t* b) {
    asm volatile(
        "mma.sync.aligned.m16n8k16.row.col.f32.bf16.bf16.f32 "
        "{%0,%1,%2,%3}, {%4,%5,%6,%7}, {%8,%9}, {%0,%1,%2,%3};"
        : "+f"(d[0]), "+f"(d[1]), "+f"(d[2]), "+f"(d[3])
        : "r"(a[0]), "r"(a[1]), "r"(a[2]), "r"(a[3]), "r"(b[0]), "r"(b[1]));
}

__device__ __forceinline__ void cp_async16(uint32_t dst, const void* src) {
    asm volatile("cp.async.ca.shared.global [%0], [%1], 16;"
        :: "r"(dst), "l"(src));
}

// split two fp32 into packed bf16 hi-word and lo-word (elem0 in low half)
__device__ __forceinline__ void split2(float a, float b, uint32_t& h, uint32_t& l) {
    __nv_bfloat16 ha = __float2bfloat16(a), hb = __float2bfloat16(b);
    float la = a - __bfloat162float(ha), lb = b - __bfloat162float(hb);
    __nv_bfloat16 lA = __float2bfloat16(la), lB = __float2bfloat16(lb);
    h = (uint32_t)__bfloat16_as_ushort(ha) | ((uint32_t)__bfloat16_as_ushort(hb) << 16);
    l = (uint32_t)__bfloat16_as_ushort(lA) | ((uint32_t)__bfloat16_as_ushort(lB) << 16);
}

// convert 8 consecutive floats -> uint4 hi + uint4 lo
__device__ __forceinline__ void stage8(const float* s, void* dh, void* dl) {
    uint32_t h[4], l[4];
    #pragma unroll
    for (int p = 0; p < 4; p++) split2(s[2*p], s[2*p+1], h[p], l[p]);
    *(uint4*)dh = make_uint4(h[0], h[1], h[2], h[3]);
    *(uint4*)dl = make_uint4(l[0], l[1], l[2], l[3]);
}

// convert 8 consecutive floats -> uint4 hi only
__device__ __forceinline__ void stage8h(const float* s, void* dh) {
    uint32_t h[4];
    #pragma unroll
    for (int p = 0; p < 4; p++) {
        __nv_bfloat16 a = __float2bfloat16(s[2*p]), b = __float2bfloat16(s[2*p+1]);
        h[p] = (uint32_t)__bfloat16_as_ushort(a) | ((uint32_t)__bfloat16_as_ushort(b) << 16);
    }
    *(uint4*)dh = make_uint4(h[0], h[1], h[2], h[3]);
}

// ---------------------------------------------------------------------------
// Kernel 0: convert 5 weight matrices into bf16 hi/lo, padded stride 136.
// ---------------------------------------------------------------------------
__global__ __launch_bounds__(256) void convw_kernel(
    const float* __restrict__ wq, const float* __restrict__ wk,
    const float* __restrict__ wv, const float* __restrict__ wg,
    const float* __restrict__ wo)
{
    int m = blockIdx.x;
    const float* src = (m == 0) ? wq : (m == 1) ? wk : (m == 2) ? wv : (m == 3) ? wg : wo;
    for (int idx = threadIdx.x; idx < 128 * 64; idx += 256) {
        int r = idx >> 6, cp = (idx & 63) * 2;
        uint32_t h, l;
        split2(src[r * 128 + cp], src[r * 128 + cp + 1], h, l);
        *(uint32_t*)&g_Wh[m][r][cp] = h;
        *(uint32_t*)&g_Wl[m][r][cp] = l;
    }
}

// ---------------------------------------------------------------------------
// GEMM tile geometry (64-row M-tile, 2 CTAs/SM):
//   smem: XH [64][136], XL [64][136], WH [128][136], WL [128][136] = 102 KB
//   block = 256 thr (8 warps): mi = w&3 (16 rows), nh = w>>2 (64 n-cols)
// ---------------------------------------------------------------------------
#define GX_XH 0
#define GX_XL 17408
#define GX_WH 34816
#define GX_WL 69632
#define GX_SMEM 104448

// ---------------------------------------------------------------------------
// Kernel 1: projections. grid = (1024 row-tiles, 4 modes).
// ---------------------------------------------------------------------------
__global__ __launch_bounds__(256) void mma_proj_kernel(
    const float* __restrict__ qx, const float* __restrict__ kvx,
    const float* __restrict__ bg)
{
    extern __shared__ __align__(16) char smem[];
    const int tid = threadIdx.x, w = tid >> 5, lane = tid & 31;
    const int mi = w & 3, nh = w >> 2;
    const int mode = blockIdx.y;
    const int r0 = blockIdx.x * 64;
    const uint32_t sb = smem_u32(smem);

    // prefetch W hi/lo via cp.async (overlaps with X conversion below)
    {
        const char* srcH = (const char*)g_Wh[mode];
        const char* srcL = (const char*)g_Wl[mode];
        for (int i = tid; i < 2176; i += 256) {
            cp_async16(sb + GX_WH + i * 16, srcH + i * 16);
            cp_async16(sb + GX_WL + i * 16, srcL + i * 16);
        }
        asm volatile("cp.async.commit_group;");
    }

    // stage X (64 rows x 128 cols) hi/lo
    {
        const float* X = (mode == 0 || mode == 3) ? qx : kvx;
        int r = tid >> 2, c0 = (tid & 3) * 32;
        const float* src = X + (size_t)(r0 + r) * CIN + c0;
        __nv_bfloat16* dh = (__nv_bfloat16*)(smem + GX_XH) + r * 136 + c0;
        __nv_bfloat16* dl = (__nv_bfloat16*)(smem + GX_XL) + r * 136 + c0;
        float buf[8];
        #pragma unroll
        for (int i = 0; i < 32; i += 8) {
            *(float4*)&buf[0] = *(const float4*)(src + i);
            *(float4*)&buf[4] = *(const float4*)(src + i + 4);
            stage8(buf, dh + i, dl + i);
        }
    }
    asm volatile("cp.async.wait_group 0;" ::: "memory");
    __syncthreads();

    const int lt = lane >> 3, lr = lane & 7;
    const uint32_t a_off = ((uint32_t)(mi * 16 + ((lt & 1) ? 8 : 0) + lr) * 136
                           + ((lt & 2) ? 8 : 0)) * 2;
    const uint32_t b_off = ((uint32_t)(((lt & 2) ? 8 : 0) + lr) * 136
                           + ((lt & 1) ? 8 : 0)) * 2 + (uint32_t)nh * 17408;
    const float SCALE = 0.17677669529663687f;

    float acc[8][4];
    #pragma unroll
    for (int f = 0; f < 8; f++)
        #pragma unroll
        for (int i = 0; i < 4; i++) acc[f][i] = 0.f;

    #pragma unroll
    for (int k = 0; k < 8; k++) {
        uint32_t ah[4], al[4];
        ldsm_x4(ah, sb + GX_XH + a_off + k * 32);
        ldsm_x4(al, sb + GX_XL + a_off + k * 32);
        #pragma unroll
        for (int ng = 0; ng < 4; ng++) {
            uint32_t bh[4], bl[4];
            uint32_t ba = sb + GX_WH + b_off + ng * 4352 + k * 32;
            ldsm_x4(bh, ba);
            ldsm_x4(bl, ba + (GX_WL - GX_WH));
            mma_bf16(acc[2*ng],   ah, bh); mma_bf16(acc[2*ng+1], ah, bh+2);
            mma_bf16(acc[2*ng],   ah, bl); mma_bf16(acc[2*ng+1], ah, bl+2);
            mma_bf16(acc[2*ng],   al, bh); mma_bf16(acc[2*ng+1], al, bh+2);
        }
    }

    const int rid_lo = r0 + mi * 16 + (lane >> 2);
    const int rid_hi = rid_lo + 8;
    const int n_lo = rid_lo >> 8, q_lo = rid_lo & 255;
    const int n_hi = rid_hi >> 8, q_hi = rid_hi & 255;

    if (mode < 3) {
        float sc = (mode == 0) ? SCALE : 1.f;
        float* dstb = (mode == 0) ? g_Q : (mode == 1) ? g_K : g_V;
        #pragma unroll
        for (int f = 0; f < 8; f++) {
            int j = nh * 64 + f * 8 + 2 * (lane & 3);
            int hh = j >> 5, d = j & 31;
            float2 v0 = {acc[f][0] * sc, acc[f][1] * sc};
            float2 v1 = {acc[f][2] * sc, acc[f][3] * sc};
            *(float2*)(dstb + ((size_t)(n_lo * NH + hh) * NN + q_lo) * HD + d) = v0;
            *(float2*)(dstb + ((size_t)(n_hi * NH + hh) * NN + q_hi) * HD + d) = v1;
        }
    } else {
        #pragma unroll
        for (int f = 0; f < 8; f++) {
            int j = nh * 64 + f * 8 + 2 * (lane & 3);
            float b0 = bg[j], b1 = bg[j + 1];
            float2 v0 = {1.f / (1.f + __expf(-(acc[f][0] + b0))),
                         1.f / (1.f + __expf(-(acc[f][1] + b1)))};
            float2 v1 = {1.f / (1.f + __expf(-(acc[f][2] + b0))),
                         1.f / (1.f + __expf(-(acc[f][3] + b1)))};
            *(float2*)(g_G + (size_t)rid_lo * NE + j) = v0;
            *(float2*)(g_G + (size_t)rid_hi * NE + j) = v1;
        }
    }
}

// ---------------------------------------------------------------------------
// Kernel 2: attention (unchanged from Round 6). grid=(2, NH, NN), block=256.
// ---------------------------------------------------------------------------
#define AT_QH 0
#define AT_KH 10240
#define AT_VH 30720
#define AT_VL 47616
#define AT_SMEM 64512

__global__ __launch_bounds__(256, 3) void mma_attn_kernel(
    const float* __restrict__ mb, const float* __restrict__ tb)
{
    extern __shared__ __align__(16) char smem[];
    const int tid = threadIdx.x, w = tid >> 5, lane = tid & 31;
    const int q0 = blockIdx.x * 128;
    const int h  = blockIdx.y;
    const int n  = blockIdx.z;

    const float* baseQ = g_Q + (size_t)(n * NH + h) * NN * HD;
    const float* baseK = g_K + (size_t)(n * NH + h) * NN * HD;
    const float* baseV = g_V + (size_t)(n * NH + h) * NN * HD;

    {
        int r = tid >> 1, c0 = (tid & 1) * 16;
        const float* src = baseQ + (size_t)(q0 + r) * HD + c0;
        __nv_bfloat16* dh = (__nv_bfloat16*)(smem + AT_QH) + r * 40 + c0;
        float buf[8];
        #pragma unroll
        for (int i = 0; i < 16; i += 8) {
            *(float4*)&buf[0] = *(const float4*)(src + i);
            *(float4*)&buf[4] = *(const float4*)(src + i + 4);
            stage8h(buf, dh + i);
        }
    }
    {
        const float* src = baseK + (size_t)tid * HD;
        __nv_bfloat16* dh = (__nv_bfloat16*)(smem + AT_KH) + tid * 40;
        float buf[8];
        #pragma unroll
        for (int i = 0; i < 32; i += 8) {
            *(float4*)&buf[0] = *(const float4*)(src + i);
            *(float4*)&buf[4] = *(const float4*)(src + i + 4);
            stage8h(buf, dh + i);
        }
    }
    {
        const float* src = baseV + (size_t)tid * HD;
        __nv_bfloat16* vh = (__nv_bfloat16*)(smem + AT_VH);
        __nv_bfloat16* vl = (__nv_bfloat16*)(smem + AT_VL);
        #pragma unroll
        for (int d = 0; d < 32; d++) {
            float x = src[d];
            __nv_bfloat16 xh = __float2bfloat16(x);
            __nv_bfloat16 xl = __float2bfloat16(x - __bfloat162float(xh));
            vh[d * 264 + tid] = xh;
            vl[d * 264 + tid] = xl;
        }
    }
    __syncthreads();

    const uint32_t sb = smem_u32(smem);
    const int lt = lane >> 3, lr = lane & 7;
    const uint32_t aq_off  = ((w * 16 + ((lt & 1) ? 8 : 0) + lr) * 40 + ((lt & 2) ? 8 : 0)) * 2;
    const uint32_t bk_off  = ((((lt & 2) ? 8 : 0) + lr) * 40  + ((lt & 1) ? 8 : 0)) * 2;
    const uint32_t bv_off  = ((((lt & 2) ? 8 : 0) + lr) * 264 + ((lt & 1) ? 8 : 0)) * 2;

    uint32_t aQh[2][4];
    #pragma unroll
    for (int kd = 0; kd < 2; kd++)
        ldsm_x4(aQh[kd], sb + AT_QH + aq_off + kd * 32);

    const int qlo = q0 + w * 16 + (lane >> 2);
    const int qhi = qlo + 8;
    const float* mrow  = mb + (size_t)n * NN;
    const float* trow0 = tb + ((size_t)h * NN + qlo) * NN;
    const float* trow1 = tb + ((size_t)h * NN + qhi) * NN;

    float oacc[4][4];
    #pragma unroll
    for (int f = 0; f < 4; f++)
        #pragma unroll
        for (int i = 0; i < 4; i++) oacc[f][i] = 0.f;
    float sum0 = 0.f, sum1 = 0.f;

    #pragma unroll 1
    for (int c = 0; c < 4; c++) {
        const int kc0 = c * 64;
        float sacc[8][4];
        #pragma unroll
        for (int f = 0; f < 8; f++)
            #pragma unroll
            for (int i = 0; i < 4; i++) sacc[f][i] = 0.f;

        #pragma unroll
        for (int kd = 0; kd < 2; kd++) {
            #pragma unroll
            for (int ng = 0; ng < 4; ng++) {
                uint32_t bh[4];
                ldsm_x4(bh, sb + AT_KH + bk_off + (uint32_t)(kc0 + ng * 16) * 80 + kd * 32);
                mma_bf16(sacc[2*ng],   aQh[kd], bh);
                mma_bf16(sacc[2*ng+1], aQh[kd], bh+2);
            }
        }

        #pragma unroll
        for (int f = 0; f < 8; f++) {
            int kcol = kc0 + f * 8 + 2 * (lane & 3);
            float2 mv = *(const float2*)(mrow  + kcol);
            float2 t0 = *(const float2*)(trow0 + kcol);
            float2 t1 = *(const float2*)(trow1 + kcol);
            sacc[f][0] = __expf(sacc[f][0] + mv.x + t0.x);
            sacc[f][1] = __expf(sacc[f][1] + mv.y + t0.y);
            sacc[f][2] = __expf(sacc[f][2] + mv.x + t1.x);
            sacc[f][3] = __expf(sacc[f][3] + mv.y + t1.y);
            sum0 += sacc[f][0] + sacc[f][1];
            sum1 += sacc[f][2] + sacc[f][3];
        }

        #pragma unroll
        for (int kf = 0; kf < 4; kf++) {
            uint32_t ph[4], pl[4];
            split2(sacc[2*kf][0],   sacc[2*kf][1],   ph[0], pl[0]);
            split2(sacc[2*kf][2],   sacc[2*kf][3],   ph[1], pl[1]);
            split2(sacc[2*kf+1][0], sacc[2*kf+1][1], ph[2], pl[2]);
            split2(sacc[2*kf+1][2], sacc[2*kf+1][3], ph[3], pl[3]);
            uint32_t kbyte = (uint32_t)(kc0 + kf * 16) * 2;
            #pragma unroll
            for (int ngd = 0; ngd < 2; ngd++) {
                uint32_t bh[4], bl[4];
                uint32_t ba = sb + AT_VH + bv_off + ngd * 16 * 528 + kbyte;
                ldsm_x4(bh, ba);
                ldsm_x4(bl, ba + (AT_VL - AT_VH));
                mma_bf16(oacc[2*ngd],   ph, bh); mma_bf16(oacc[2*ngd+1], ph, bh+2);
                mma_bf16(oacc[2*ngd],   ph, bl); mma_bf16(oacc[2*ngd+1], ph, bl+2);
                mma_bf16(oacc[2*ngd],   pl, bh); mma_bf16(oacc[2*ngd+1], pl, bh+2);
            }
        }
    }

    sum0 += __shfl_xor_sync(0xffffffffu, sum0, 1);
    sum0 += __shfl_xor_sync(0xffffffffu, sum0, 2);
    sum1 += __shfl_xor_sync(0xffffffffu, sum1, 1);
    sum1 += __shfl_xor_sync(0xffffffffu, sum1, 2);
    float inv0 = 1.f / sum0, inv1 = 1.f / sum1;

    const int rid_lo = n * NN + qlo, rid_hi = n * NN + qhi;
    #pragma unroll
    for (int f = 0; f < 4; f++) {
        int d = f * 8 + 2 * (lane & 3);
        float2 glo = *(const float2*)(g_G + (size_t)rid_lo * NE + h * HD + d);
        float2 ghi = *(const float2*)(g_G + (size_t)rid_hi * NE + h * HD + d);
        float2 o0 = {oacc[f][0] * inv0 * glo.x, oacc[f][1] * inv0 * glo.y};
        float2 o1 = {oacc[f][2] * inv1 * ghi.x, oacc[f][3] * inv1 * ghi.y};
        *(float2*)(g_O + (size_t)rid_lo * NE + h * HD + d) = o0;
        *(float2*)(g_O + (size_t)rid_hi * NE + h * HD + d) = o1;
    }
}

// ---------------------------------------------------------------------------
// Kernel 3: output projection. grid = 1024, block = 256, 64-row tiles.
// ---------------------------------------------------------------------------
__global__ __launch_bounds__(256) void mma_out_kernel(
    const float* __restrict__ bo, float* __restrict__ out)
{
    extern __shared__ __align__(16) char smem[];
    const int tid = threadIdx.x, w = tid >> 5, lane = tid & 31;
    const int mi = w & 3, nh = w >> 2;
    const int r0 = blockIdx.x * 64;
    const uint32_t sb = smem_u32(smem);

    {
        const char* srcH = (const char*)g_Wh[4];
        const char* srcL = (const char*)g_Wl[4];
        for (int i = tid; i < 2176; i += 256) {
            cp_async16(sb + GX_WH + i * 16, srcH + i * 16);
            cp_async16(sb + GX_WL + i * 16, srcL + i * 16);
        }
        asm volatile("cp.async.commit_group;");
    }
    {
        int r = tid >> 2, c0 = (tid & 3) * 32;
        const float* src = g_O + (size_t)(r0 + r) * NE + c0;
        __nv_bfloat16* dh = (__nv_bfloat16*)(smem + GX_XH) + r * 136 + c0;
        __nv_bfloat16* dl = (__nv_bfloat16*)(smem + GX_XL) + r * 136 + c0;
        float buf[8];
        #pragma unroll
        for (int i = 0; i < 32; i += 8) {
            *(float4*)&buf[0] = *(const float4*)(src + i);
            *(float4*)&buf[4] = *(const float4*)(src + i + 4);
            stage8(buf, dh + i, dl + i);
        }
    }
    asm volatile("cp.async.wait_group 0;" ::: "memory");
    __syncthreads();

    const int lt = lane >> 3, lr = lane & 7;
    const uint32_t a_off = ((uint32_t)(mi * 16 + ((lt & 1) ? 8 : 0) + lr) * 136
                           + ((lt & 2) ? 8 : 0)) * 2;
    const uint32_t b_off = ((uint32_t)(((lt & 2) ? 8 : 0) + lr) * 136
                           + ((lt & 1) ? 8 : 0)) * 2 + (uint32_t)nh * 17408;

    float acc[8][4];
    #pragma unroll
    for (int f = 0; f < 8; f++)
        #pragma unroll
        for (int i = 0; i < 4; i++) acc[f][i] = 0.f;

    #pragma unroll
    for (int k = 0; k < 8; k++) {
        uint32_t ah[4], al[4];
        ldsm_x4(ah, sb + GX_XH + a_off + k * 32);
        ldsm_x4(al, sb + GX_XL + a_off + k * 32);
        #pragma unroll
        for (int ng = 0; ng < 4; ng++) {
            uint32_t bh[4], bl[4];
            uint32_t ba = sb + GX_WH + b_off + ng * 4352 + k * 32;
            ldsm_x4(bh, ba);
            ldsm_x4(bl, ba + (GX_WL - GX_WH));
            mma_bf16(acc[2*ng],   ah, bh); mma_bf16(acc[2*ng+1], ah, bh+2);
            mma_bf16(acc[2*ng],   ah, bl); mma_bf16(acc[2*ng+1], ah, bl+2);
            mma_bf16(acc[2*ng],   al, bh); mma_bf16(acc[2*ng+1], al, bh+2);
        }
    }

    const int rid_lo = r0 + mi * 16 + (lane >> 2);
    const int rid_hi = rid_lo + 8;
    #pragma unroll
    for (int f = 0; f < 8; f++) {
        int cc = nh * 64 + f * 8 + 2 * (lane & 3);
        float b0 = bo[cc], b1 = bo[cc + 1];
        *(float2*)(out + (size_t)rid_lo * CIN + cc) = make_float2(acc[f][0] + b0, acc[f][1] + b1);
        *(float2*)(out + (size_t)rid_hi * CIN + cc) = make_float2(acc[f][2] + b0, acc[f][3] + b1);
    }
}

// ---------------------------------------------------------------------------
extern "C" void kernel_launch(void* const* d_in, const int* in_sizes, int n_in,
                              void* d_out, int out_size)
{
    const float* qx  = (const float*)d_in[0];
    const float* kvx = (const float*)d_in[1];
    const float* mb  = (const float*)d_in[2];
    const float* tb  = (const float*)d_in[3];
    const float* wq  = (const float*)d_in[4];
    const float* wk  = (const float*)d_in[5];
    const float* wv  = (const float*)d_in[6];
    const float* wg  = (const float*)d_in[7];
    const float* bg  = (const float*)d_in[8];
    const float* wo  = (const float*)d_in[9];
    const float* bo  = (const float*)d_in[10];
    float* out = (float*)d_out;

    cudaFuncSetAttribute(mma_proj_kernel, cudaFuncAttributeMaxDynamicSharedMemorySize, GX_SMEM);
    cudaFuncSetAttribute(mma_attn_kernel, cudaFuncAttributeMaxDynamicSharedMemorySize, AT_SMEM);
    cudaFuncSetAttribute(mma_out_kernel,  cudaFuncAttributeMaxDynamicSharedMemorySize, GX_SMEM);

    convw_kernel<<<5, 256>>>(wq, wk, wv, wg, wo);
    mma_proj_kernel<<<dim3(1024, 4), 256, GX_SMEM>>>(qx, kvx, bg);
    mma_attn_kernel<<<dim3(2, NH, NN), 256, AT_SMEM>>>(mb, tb);
    mma_out_kernel<<<1024, 256, GX_SMEM>>>(bo, out);
}

// round 8
// speedup vs baseline: 3.0368x; 1.1606x over previous
#include <cuda_runtime.h>
#include <cuda_bf16.h>
#include <cstdint>
#include <math.h>

#define NN  256
#define CIN 128
#define NH  4
#define HD  32
#define NE  128

// Scratch (allocation-free rule)
__device__ float g_Q[NN*NH*NN*HD];   // [n][h][q][d], pre-scaled
__device__ float g_K[NN*NH*NN*HD];   // [n][h][k][d]
__device__ float g_V[NN*NH*NN*HD];   // [n][h][k][d]
__device__ float g_G[NN*NN*NE];      // sigmoid gate [rid][e]
__device__ float g_O[NN*NN*NE];      // gated attention out [rid][e]
__device__ __align__(16) __nv_bfloat16 g_Wh[5][128][136];  // wq,wk,wv,wg,wo hi
__device__ __align__(16) __nv_bfloat16 g_Wl[5][128][136];  // lo

// ---------------------------------------------------------------------------
// helpers
// ---------------------------------------------------------------------------
__device__ __forceinline__ uint32_t smem_u32(const void* p) {
    uint32_t a;
    asm("{ .reg .u64 t; cvta.to.shared.u64 t, %1; cvt.u32.u64 %0, t; }"
        : "=r"(a) : "l"(p));
    return a;
}

__device__ __forceinline__ void ldsm_x4(uint32_t* r, uint32_t addr) {
    asm volatile("ldmatrix.sync.aligned.m8n8.x4.shared.b16 {%0,%1,%2,%3}, [%4];"
        : "=r"(r[0]), "=r"(r[1]), "=r"(r[2]), "=r"(r[3]) : "r"(addr));
}

__device__ __forceinline__ void mma_bf16(float* d, const uint32_t* a, const uint32_t* b) {
    asm volatile(
        "mma.sync.aligned.m16n8k16.row.col.f32.bf16.bf16.f32 "
        "{%0,%1,%2,%3}, {%4,%5,%6,%7}, {%8,%9}, {%0,%1,%2,%3};"
        : "+f"(d[0]), "+f"(d[1]), "+f"(d[2]), "+f"(d[3])
        : "r"(a[0]), "r"(a[1]), "r"(a[2]), "r"(a[3]), "r"(b[0]), "r"(b[1]));
}

__device__ __forceinline__ void cp_async16(uint32_t dst, const void* src) {
    asm volatile("cp.async.ca.shared.global [%0], [%1], 16;"
        :: "r"(dst), "l"(src));
}

// split two fp32 into packed bf16 hi-word and lo-word (elem0 in low half)
__device__ __forceinline__ void split2(float a, float b, uint32_t& h, uint32_t& l) {
    __nv_bfloat16 ha = __float2bfloat16(a), hb = __float2bfloat16(b);
    float la = a - __bfloat162float(ha), lb = b - __bfloat162float(hb);
    __nv_bfloat16 lA = __float2bfloat16(la), lB = __float2bfloat16(lb);
    h = (uint32_t)__bfloat16_as_ushort(ha) | ((uint32_t)__bfloat16_as_ushort(hb) << 16);
    l = (uint32_t)__bfloat16_as_ushort(lA) | ((uint32_t)__bfloat16_as_ushort(lB) << 16);
}

// convert 8 consecutive floats -> uint4 hi + uint4 lo
__device__ __forceinline__ void stage8(const float* s, void* dh, void* dl) {
    uint32_t h[4], l[4];
    #pragma unroll
    for (int p = 0; p < 4; p++) split2(s[2*p], s[2*p+1], h[p], l[p]);
    *(uint4*)dh = make_uint4(h[0], h[1], h[2], h[3]);
    *(uint4*)dl = make_uint4(l[0], l[1], l[2], l[3]);
}

// convert 8 consecutive floats -> uint4 hi only
__device__ __forceinline__ void stage8h(const float* s, void* dh) {
    uint32_t h[4];
    #pragma unroll
    for (int p = 0; p < 4; p++) {
        __nv_bfloat16 a = __float2bfloat16(s[2*p]), b = __float2bfloat16(s[2*p+1]);
        h[p] = (uint32_t)__bfloat16_as_ushort(a) | ((uint32_t)__bfloat16_as_ushort(b) << 16);
    }
    *(uint4*)dh = make_uint4(h[0], h[1], h[2], h[3]);
}

// ---------------------------------------------------------------------------
// Kernel 0: convert 5 weight matrices into bf16 hi/lo, padded stride 136.
// ---------------------------------------------------------------------------
__global__ __launch_bounds__(256) void convw_kernel(
    const float* __restrict__ wq, const float* __restrict__ wk,
    const float* __restrict__ wv, const float* __restrict__ wg,
    const float* __restrict__ wo)
{
    int m = blockIdx.x;
    const float* src = (m == 0) ? wq : (m == 1) ? wk : (m == 2) ? wv : (m == 3) ? wg : wo;
    for (int idx = threadIdx.x; idx < 128 * 64; idx += 256) {
        int r = idx >> 6, cp = (idx & 63) * 2;
        uint32_t h, l;
        split2(src[r * 128 + cp], src[r * 128 + cp + 1], h, l);
        *(uint32_t*)&g_Wh[m][r][cp] = h;
        *(uint32_t*)&g_Wl[m][r][cp] = l;
    }
}

// ---------------------------------------------------------------------------
// GEMM tile geometry: M-tile 64, N 128, block 256 (8 warps): warp = 32m x 32n.
//   mi = w&1 (m-group of 32), nh = w>>1 (n-group of 32)
// smem: XH [64][136], XL, WH [128][136], WL = 102 KB -> 2 CTAs/SM
// ---------------------------------------------------------------------------
#define GX_XH 0
#define GX_XL 17408
#define GX_WH 34816
#define GX_WL 69632
#define GX_SMEM 104448

// ---------------------------------------------------------------------------
// Kernel 1: projections. grid = (1024 row-tiles, 4 modes).
// ---------------------------------------------------------------------------
__global__ __launch_bounds__(256) void mma_proj_kernel(
    const float* __restrict__ qx, const float* __restrict__ kvx,
    const float* __restrict__ bg)
{
    extern __shared__ __align__(16) char smem[];
    const int tid = threadIdx.x, w = tid >> 5, lane = tid & 31;
    const int mi = w & 1, nh = w >> 1;
    const int mode = blockIdx.y;
    const int r0 = blockIdx.x * 64;
    const uint32_t sb = smem_u32(smem);

    // prefetch W hi/lo via cp.async (overlaps with X conversion below)
    {
        const char* srcH = (const char*)g_Wh[mode];
        const char* srcL = (const char*)g_Wl[mode];
        for (int i = tid; i < 2176; i += 256) {
            cp_async16(sb + GX_WH + i * 16, srcH + i * 16);
            cp_async16(sb + GX_WL + i * 16, srcL + i * 16);
        }
        asm volatile("cp.async.commit_group;");
    }

    // stage X (64 rows x 128 cols) hi/lo
    {
        const float* X = (mode == 0 || mode == 3) ? qx : kvx;
        int r = tid >> 2, c0 = (tid & 3) * 32;
        const float* src = X + (size_t)(r0 + r) * CIN + c0;
        __nv_bfloat16* dh = (__nv_bfloat16*)(smem + GX_XH) + r * 136 + c0;
        __nv_bfloat16* dl = (__nv_bfloat16*)(smem + GX_XL) + r * 136 + c0;
        float buf[8];
        #pragma unroll
        for (int i = 0; i < 32; i += 8) {
            *(float4*)&buf[0] = *(const float4*)(src + i);
            *(float4*)&buf[4] = *(const float4*)(src + i + 4);
            stage8(buf, dh + i, dl + i);
        }
    }
    asm volatile("cp.async.wait_group 0;" ::: "memory");
    __syncthreads();

    const int lt = lane >> 3, lr = lane & 7;
    // A row base mi*32 (+ mf*16 later)
    const uint32_t a_off = ((uint32_t)(mi * 32 + ((lt & 1) ? 8 : 0) + lr) * 136
                           + ((lt & 2) ? 8 : 0)) * 2;
    // B row base nh*32 (+ g*16 later)
    const uint32_t b_off = ((uint32_t)(nh * 32 + ((lt & 2) ? 8 : 0) + lr) * 136
                           + ((lt & 1) ? 8 : 0)) * 2;
    const float SCALE = 0.17677669529663687f;

    float acc[2][2][2][4];   // [mf][g][j][4]
    #pragma unroll
    for (int mf = 0; mf < 2; mf++)
        #pragma unroll
        for (int g = 0; g < 2; g++)
            #pragma unroll
            for (int j = 0; j < 2; j++)
                #pragma unroll
                for (int i = 0; i < 4; i++) acc[mf][g][j][i] = 0.f;

    #pragma unroll
    for (int k = 0; k < 8; k++) {
        uint32_t ah[2][4], al[2][4];
        #pragma unroll
        for (int mf = 0; mf < 2; mf++) {
            ldsm_x4(ah[mf], sb + GX_XH + a_off + mf * 4352 + k * 32);
            ldsm_x4(al[mf], sb + GX_XL + a_off + mf * 4352 + k * 32);
        }
        #pragma unroll
        for (int g = 0; g < 2; g++) {
            uint32_t bh[4], bl[4];
            uint32_t ba = sb + GX_WH + b_off + g * 4352 + k * 32;
            ldsm_x4(bh, ba);
            ldsm_x4(bl, ba + (GX_WL - GX_WH));
            #pragma unroll
            for (int mf = 0; mf < 2; mf++) {
                mma_bf16(acc[mf][g][0], ah[mf], bh); mma_bf16(acc[mf][g][1], ah[mf], bh+2);
                mma_bf16(acc[mf][g][0], ah[mf], bl); mma_bf16(acc[mf][g][1], ah[mf], bl+2);
                mma_bf16(acc[mf][g][0], al[mf], bh); mma_bf16(acc[mf][g][1], al[mf], bh+2);
            }
        }
    }

    #pragma unroll
    for (int mf = 0; mf < 2; mf++) {
        const int rlo = r0 + mi * 32 + mf * 16 + (lane >> 2);
        const int rhi = rlo + 8;
        const int n_lo = rlo >> 8, q_lo = rlo & 255;
        const int n_hi = rhi >> 8, q_hi = rhi & 255;
        #pragma unroll
        for (int g = 0; g < 2; g++)
            #pragma unroll
            for (int j = 0; j < 2; j++) {
                int col = nh * 32 + g * 16 + j * 8 + 2 * (lane & 3);
                float* a = acc[mf][g][j];
                if (mode < 3) {
                    float sc = (mode == 0) ? SCALE : 1.f;
                    float* dstb = (mode == 0) ? g_Q : (mode == 1) ? g_K : g_V;
                    int hh = col >> 5, d = col & 31;
                    *(float2*)(dstb + ((size_t)(n_lo * NH + hh) * NN + q_lo) * HD + d)
                        = make_float2(a[0] * sc, a[1] * sc);
                    *(float2*)(dstb + ((size_t)(n_hi * NH + hh) * NN + q_hi) * HD + d)
                        = make_float2(a[2] * sc, a[3] * sc);
                } else {
                    float b0 = bg[col], b1 = bg[col + 1];
                    *(float2*)(g_G + (size_t)rlo * NE + col) = make_float2(
                        1.f / (1.f + __expf(-(a[0] + b0))),
                        1.f / (1.f + __expf(-(a[1] + b1))));
                    *(float2*)(g_G + (size_t)rhi * NE + col) = make_float2(
                        1.f / (1.f + __expf(-(a[2] + b0))),
                        1.f / (1.f + __expf(-(a[3] + b1))));
                }
            }
    }
}

// ---------------------------------------------------------------------------
// Kernel 2: attention. grid=(NH, NN), block=256 (8 warps x 32 q = all 256 q).
// Q,K single bf16; no max-subtraction; V hi/lo, P hi/lo, 3-split PV.
// smem: QH [256][40], KH [256][40], VH/VL [32][264] = 73 KB -> 2 CTA/SM
// ---------------------------------------------------------------------------
#define AT_QH 0
#define AT_KH 20480
#define AT_VH 40960
#define AT_VL 57856
#define AT_SMEM 74752

__global__ __launch_bounds__(256, 2) void mma_attn_kernel(
    const float* __restrict__ mb, const float* __restrict__ tb)
{
    extern __shared__ __align__(16) char smem[];
    const int tid = threadIdx.x, w = tid >> 5, lane = tid & 31;
    const int h = blockIdx.x;
    const int n = blockIdx.y;

    const float* baseQ = g_Q + (size_t)(n * NH + h) * NN * HD;
    const float* baseK = g_K + (size_t)(n * NH + h) * NN * HD;
    const float* baseV = g_V + (size_t)(n * NH + h) * NN * HD;

    // --- stage Q hi (256 rows, thread = row) ---
    {
        const float* src = baseQ + (size_t)tid * HD;
        __nv_bfloat16* dh = (__nv_bfloat16*)(smem + AT_QH) + tid * 40;
        float buf[8];
        #pragma unroll
        for (int i = 0; i < 32; i += 8) {
            *(float4*)&buf[0] = *(const float4*)(src + i);
            *(float4*)&buf[4] = *(const float4*)(src + i + 4);
            stage8h(buf, dh + i);
        }
    }
    // --- stage K hi ---
    {
        const float* src = baseK + (size_t)tid * HD;
        __nv_bfloat16* dh = (__nv_bfloat16*)(smem + AT_KH) + tid * 40;
        float buf[8];
        #pragma unroll
        for (int i = 0; i < 32; i += 8) {
            *(float4*)&buf[0] = *(const float4*)(src + i);
            *(float4*)&buf[4] = *(const float4*)(src + i + 4);
            stage8h(buf, dh + i);
        }
    }
    // --- stage V transposed hi/lo ---
    {
        const float* src = baseV + (size_t)tid * HD;
        __nv_bfloat16* vh = (__nv_bfloat16*)(smem + AT_VH);
        __nv_bfloat16* vl = (__nv_bfloat16*)(smem + AT_VL);
        #pragma unroll
        for (int d = 0; d < 32; d++) {
            float x = src[d];
            __nv_bfloat16 xh = __float2bfloat16(x);
            __nv_bfloat16 xl = __float2bfloat16(x - __bfloat162float(xh));
            vh[d * 264 + tid] = xh;
            vl[d * 264 + tid] = xl;
        }
    }
    __syncthreads();

    const uint32_t sb = smem_u32(smem);
    const int lt = lane >> 3, lr = lane & 7;
    const uint32_t bk_off = ((((lt & 2) ? 8 : 0) + lr) * 40  + ((lt & 1) ? 8 : 0)) * 2;
    const uint32_t bv_off = ((((lt & 2) ? 8 : 0) + lr) * 264 + ((lt & 1) ? 8 : 0)) * 2;

    // Q fragments: 2 m16 frags (rows w*32 + mf*16 ...), 2 kd halves of d32
    uint32_t aQh[2][2][4];
    #pragma unroll
    for (int mf = 0; mf < 2; mf++) {
        uint32_t aq_off = ((uint32_t)(w * 32 + mf * 16 + ((lt & 1) ? 8 : 0) + lr) * 40
                          + ((lt & 2) ? 8 : 0)) * 2;
        ldsm_x4(aQh[mf][0], sb + AT_QH + aq_off);
        ldsm_x4(aQh[mf][1], sb + AT_QH + aq_off + 32);
    }

    // 4 q rows owned by this thread: (mf, half)
    const int qr00 = w * 32 + (lane >> 2);         // mf0 lo
    const float* mrow = mb + (size_t)n * NN;
    const float* tr00 = tb + ((size_t)h * NN + qr00) * NN;
    const float* tr01 = tr00 + 8 * NN;
    const float* tr10 = tr00 + 16 * NN;
    const float* tr11 = tr00 + 24 * NN;

    float oacc[2][4][4];    // [mf][f over 4 n8 of d32][4]
    #pragma unroll
    for (int mf = 0; mf < 2; mf++)
        #pragma unroll
        for (int f = 0; f < 4; f++)
            #pragma unroll
            for (int i = 0; i < 4; i++) oacc[mf][f][i] = 0.f;
    float s00 = 0.f, s01 = 0.f, s10 = 0.f, s11 = 0.f;

    #pragma unroll 1
    for (int c = 0; c < 8; c++) {                 // 32-key chunks
        const int kc0 = c * 32;
        float sacc[2][4][4];                       // [mf][f over 4 n8][4]
        #pragma unroll
        for (int mf = 0; mf < 2; mf++)
            #pragma unroll
            for (int f = 0; f < 4; f++)
                #pragma unroll
                for (int i = 0; i < 4; i++) sacc[mf][f][i] = 0.f;

        // S = Q K^T
        #pragma unroll
        for (int kd = 0; kd < 2; kd++) {
            #pragma unroll
            for (int g = 0; g < 2; g++) {          // key16 groups in chunk
                uint32_t bh[4];
                ldsm_x4(bh, sb + AT_KH + bk_off + (uint32_t)(kc0 + g * 16) * 80 + kd * 32);
                #pragma unroll
                for (int mf = 0; mf < 2; mf++) {
                    mma_bf16(sacc[mf][2*g],   aQh[mf][kd], bh);
                    mma_bf16(sacc[mf][2*g+1], aQh[mf][kd], bh+2);
                }
            }
        }

        // biases + exp + sums
        #pragma unroll
        for (int f = 0; f < 4; f++) {
            int kcol = kc0 + f * 8 + 2 * (lane & 3);
            float2 mv = *(const float2*)(mrow + kcol);
            float2 t00 = *(const float2*)(tr00 + kcol);
            float2 t01 = *(const float2*)(tr01 + kcol);
            float2 t10 = *(const float2*)(tr10 + kcol);
            float2 t11 = *(const float2*)(tr11 + kcol);
            sacc[0][f][0] = __expf(sacc[0][f][0] + mv.x + t00.x);
            sacc[0][f][1] = __expf(sacc[0][f][1] + mv.y + t00.y);
            sacc[0][f][2] = __expf(sacc[0][f][2] + mv.x + t01.x);
            sacc[0][f][3] = __expf(sacc[0][f][3] + mv.y + t01.y);
            sacc[1][f][0] = __expf(sacc[1][f][0] + mv.x + t10.x);
            sacc[1][f][1] = __expf(sacc[1][f][1] + mv.y + t10.y);
            sacc[1][f][2] = __expf(sacc[1][f][2] + mv.x + t11.x);
            sacc[1][f][3] = __expf(sacc[1][f][3] + mv.y + t11.y);
            s00 += sacc[0][f][0] + sacc[0][f][1];
            s01 += sacc[0][f][2] + sacc[0][f][3];
            s10 += sacc[1][f][0] + sacc[1][f][1];
            s11 += sacc[1][f][2] + sacc[1][f][3];
        }

        // O += P V (3-split)
        #pragma unroll
        for (int kf = 0; kf < 2; kf++) {           // k16 groups in chunk
            uint32_t ph[2][4], pl[2][4];
            #pragma unroll
            for (int mf = 0; mf < 2; mf++) {
                split2(sacc[mf][2*kf][0],   sacc[mf][2*kf][1],   ph[mf][0], pl[mf][0]);
                split2(sacc[mf][2*kf][2],   sacc[mf][2*kf][3],   ph[mf][1], pl[mf][1]);
                split2(sacc[mf][2*kf+1][0], sacc[mf][2*kf+1][1], ph[mf][2], pl[mf][2]);
                split2(sacc[mf][2*kf+1][2], sacc[mf][2*kf+1][3], ph[mf][3], pl[mf][3]);
            }
            uint32_t kbyte = (uint32_t)(kc0 + kf * 16) * 2;
            #pragma unroll
            for (int ngd = 0; ngd < 2; ngd++) {
                uint32_t bh[4], bl[4];
                uint32_t ba = sb + AT_VH + bv_off + ngd * 16 * 528 + kbyte;
                ldsm_x4(bh, ba);
                ldsm_x4(bl, ba + (AT_VL - AT_VH));
                #pragma unroll
                for (int mf = 0; mf < 2; mf++) {
                    mma_bf16(oacc[mf][2*ngd],   ph[mf], bh);
                    mma_bf16(oacc[mf][2*ngd+1], ph[mf], bh+2);
                    mma_bf16(oacc[mf][2*ngd],   ph[mf], bl);
                    mma_bf16(oacc[mf][2*ngd+1], ph[mf], bl+2);
                    mma_bf16(oacc[mf][2*ngd],   pl[mf], bh);
                    mma_bf16(oacc[mf][2*ngd+1], pl[mf], bh+2);
                }
            }
        }
    }

    s00 += __shfl_xor_sync(0xffffffffu, s00, 1);
    s00 += __shfl_xor_sync(0xffffffffu, s00, 2);
    s01 += __shfl_xor_sync(0xffffffffu, s01, 1);
    s01 += __shfl_xor_sync(0xffffffffu, s01, 2);
    s10 += __shfl_xor_sync(0xffffffffu, s10, 1);
    s10 += __shfl_xor_sync(0xffffffffu, s10, 2);
    s11 += __shfl_xor_sync(0xffffffffu, s11, 1);
    s11 += __shfl_xor_sync(0xffffffffu, s11, 2);
    float inv[2][2] = {{1.f / s00, 1.f / s01}, {1.f / s10, 1.f / s11}};

    #pragma unroll
    for (int mf = 0; mf < 2; mf++) {
        const int rlo = n * NN + w * 32 + mf * 16 + (lane >> 2);
        const int rhi = rlo + 8;
        #pragma unroll
        for (int f = 0; f < 4; f++) {
            int d = f * 8 + 2 * (lane & 3);
            float2 glo = *(const float2*)(g_G + (size_t)rlo * NE + h * HD + d);
            float2 ghi = *(const float2*)(g_G + (size_t)rhi * NE + h * HD + d);
            *(float2*)(g_O + (size_t)rlo * NE + h * HD + d) = make_float2(
                oacc[mf][f][0] * inv[mf][0] * glo.x,
                oacc[mf][f][1] * inv[mf][0] * glo.y);
            *(float2*)(g_O + (size_t)rhi * NE + h * HD + d) = make_float2(
                oacc[mf][f][2] * inv[mf][1] * ghi.x,
                oacc[mf][f][3] * inv[mf][1] * ghi.y);
        }
    }
}

// ---------------------------------------------------------------------------
// Kernel 3: output projection. grid = 1024, block = 256, warp 32m x 32n.
// ---------------------------------------------------------------------------
__global__ __launch_bounds__(256) void mma_out_kernel(
    const float* __restrict__ bo, float* __restrict__ out)
{
    extern __shared__ __align__(16) char smem[];
    const int tid = threadIdx.x, w = tid >> 5, lane = tid & 31;
    const int mi = w & 1, nh = w >> 1;
    const int r0 = blockIdx.x * 64;
    const uint32_t sb = smem_u32(smem);

    {
        const char* srcH = (const char*)g_Wh[4];
        const char* srcL = (const char*)g_Wl[4];
        for (int i = tid; i < 2176; i += 256) {
            cp_async16(sb + GX_WH + i * 16, srcH + i * 16);
            cp_async16(sb + GX_WL + i * 16, srcL + i * 16);
        }
        asm volatile("cp.async.commit_group;");
    }
    {
        int r = tid >> 2, c0 = (tid & 3) * 32;
        const float* src = g_O + (size_t)(r0 + r) * NE + c0;
        __nv_bfloat16* dh = (__nv_bfloat16*)(smem + GX_XH) + r * 136 + c0;
        __nv_bfloat16* dl = (__nv_bfloat16*)(smem + GX_XL) + r * 136 + c0;
        float buf[8];
        #pragma unroll
        for (int i = 0; i < 32; i += 8) {
            *(float4*)&buf[0] = *(const float4*)(src + i);
            *(float4*)&buf[4] = *(const float4*)(src + i + 4);
            stage8(buf, dh + i, dl + i);
        }
    }
    asm volatile("cp.async.wait_group 0;" ::: "memory");
    __syncthreads();

    const int lt = lane >> 3, lr = lane & 7;
    const uint32_t a_off = ((uint32_t)(mi * 32 + ((lt & 1) ? 8 : 0) + lr) * 136
                           + ((lt & 2) ? 8 : 0)) * 2;
    const uint32_t b_off = ((uint32_t)(nh * 32 + ((lt & 2) ? 8 : 0) + lr) * 136
                           + ((lt & 1) ? 8 : 0)) * 2;

    float acc[2][2][2][4];
    #pragma unroll
    for (int mf = 0; mf < 2; mf++)
        #pragma unroll
        for (int g = 0; g < 2; g++)
            #pragma unroll
            for (int j = 0; j < 2; j++)
                #pragma unroll
                for (int i = 0; i < 4; i++) acc[mf][g][j][i] = 0.f;

    #pragma unroll
    for (int k = 0; k < 8; k++) {
        uint32_t ah[2][4], al[2][4];
        #pragma unroll
        for (int mf = 0; mf < 2; mf++) {
            ldsm_x4(ah[mf], sb + GX_XH + a_off + mf * 4352 + k * 32);
            ldsm_x4(al[mf], sb + GX_XL + a_off + mf * 4352 + k * 32);
        }
        #pragma unroll
        for (int g = 0; g < 2; g++) {
            uint32_t bh[4], bl[4];
            uint32_t ba = sb + GX_WH + b_off + g * 4352 + k * 32;
            ldsm_x4(bh, ba);
            ldsm_x4(bl, ba + (GX_WL - GX_WH));
            #pragma unroll
            for (int mf = 0; mf < 2; mf++) {
                mma_bf16(acc[mf][g][0], ah[mf], bh); mma_bf16(acc[mf][g][1], ah[mf], bh+2);
                mma_bf16(acc[mf][g][0], ah[mf], bl); mma_bf16(acc[mf][g][1], ah[mf], bl+2);
                mma_bf16(acc[mf][g][0], al[mf], bh); mma_bf16(acc[mf][g][1], al[mf], bh+2);
            }
        }
    }

    #pragma unroll
    for (int mf = 0; mf < 2; mf++) {
        const int rlo = r0 + mi * 32 + mf * 16 + (lane >> 2);
        const int rhi = rlo + 8;
        #pragma unroll
        for (int g = 0; g < 2; g++)
            #pragma unroll
            for (int j = 0; j < 2; j++) {
                int cc = nh * 32 + g * 16 + j * 8 + 2 * (lane & 3);
                float b0 = bo[cc], b1 = bo[cc + 1];
                float* a = acc[mf][g][j];
                *(float2*)(out + (size_t)rlo * CIN + cc) = make_float2(a[0] + b0, a[1] + b1);
                *(float2*)(out + (size_t)rhi * CIN + cc) = make_float2(a[2] + b0, a[3] + b1);
            }
    }
}

// ---------------------------------------------------------------------------
extern "C" void kernel_launch(void* const* d_in, const int* in_sizes, int n_in,
                              void* d_out, int out_size)
{
    const float* qx  = (const float*)d_in[0];
    const float* kvx = (const float*)d_in[1];
    const float* mb  = (const float*)d_in[2];
    const float* tb  = (const float*)d_in[3];
    const float* wq  = (const float*)d_in[4];
    const float* wk  = (const float*)d_in[5];
    const float* wv  = (const float*)d_in[6];
    const float* wg  = (const float*)d_in[7];
    const float* bg  = (const float*)d_in[8];
    const float* wo  = (const float*)d_in[9];
    const float* bo  = (const float*)d_in[10];
    float* out = (float*)d_out;

    cudaFuncSetAttribute(mma_proj_kernel, cudaFuncAttributeMaxDynamicSharedMemorySize, GX_SMEM);
    cudaFuncSetAttribute(mma_attn_kernel, cudaFuncAttributeMaxDynamicSharedMemorySize, AT_SMEM);
    cudaFuncSetAttribute(mma_out_kernel,  cudaFuncAttributeMaxDynamicSharedMemorySize, GX_SMEM);

    convw_kernel<<<5, 256>>>(wq, wk, wv, wg, wo);
    mma_proj_kernel<<<dim3(1024, 4), 256, GX_SMEM>>>(qx, kvx, bg);
    mma_attn_kernel<<<dim3(NH, NN), 256, AT_SMEM>>>(mb, tb);
    mma_out_kernel<<<1024, 256, GX_SMEM>>>(bo, out);
}

// round 9
// speedup vs baseline: 3.4830x; 1.1469x over previous
#include <cuda_runtime.h>
#include <cuda_bf16.h>
#include <cstdint>
#include <math.h>

#define NN  256
#define CIN 128
#define NH  4
#define HD  32
#define NE  128

// Scratch (allocation-free rule)
__device__ __align__(16) __nv_bfloat16 g_Qb[NN*NH*NN*HD];   // bf16(scaled q)
__device__ __align__(16) __nv_bfloat16 g_Kb[NN*NH*NN*HD];   // bf16(k)
__device__ __align__(16) __nv_bfloat16 g_Vhb[NN*NH*NN*HD];  // v hi
__device__ __align__(16) __nv_bfloat16 g_Vlb[NN*NH*NN*HD];  // v lo
__device__ float g_G[NN*NN*NE];      // sigmoid gate [rid][e] (fp32 - precision)
__device__ float g_O[NN*NN*NE];      // gated attention out [rid][e]
__device__ __align__(16) __nv_bfloat16 g_Wh[5][128][136];   // weights hi
__device__ __align__(16) __nv_bfloat16 g_Wl[5][128][136];   // weights lo

// ---------------------------------------------------------------------------
// helpers
// ---------------------------------------------------------------------------
__device__ __forceinline__ uint32_t smem_u32(const void* p) {
    uint32_t a;
    asm("{ .reg .u64 t; cvta.to.shared.u64 t, %1; cvt.u32.u64 %0, t; }"
        : "=r"(a) : "l"(p));
    return a;
}

__device__ __forceinline__ void ldsm_x4(uint32_t* r, uint32_t addr) {
    asm volatile("ldmatrix.sync.aligned.m8n8.x4.shared.b16 {%0,%1,%2,%3}, [%4];"
        : "=r"(r[0]), "=r"(r[1]), "=r"(r[2]), "=r"(r[3]) : "r"(addr));
}

__device__ __forceinline__ void ldsm_x4_t(uint32_t* r, uint32_t addr) {
    asm volatile("ldmatrix.sync.aligned.m8n8.x4.trans.shared.b16 {%0,%1,%2,%3}, [%4];"
        : "=r"(r[0]), "=r"(r[1]), "=r"(r[2]), "=r"(r[3]) : "r"(addr));
}

__device__ __forceinline__ void mma_bf16(float* d, const uint32_t* a, const uint32_t* b) {
    asm volatile(
        "mma.sync.aligned.m16n8k16.row.col.f32.bf16.bf16.f32 "
        "{%0,%1,%2,%3}, {%4,%5,%6,%7}, {%8,%9}, {%0,%1,%2,%3};"
        : "+f"(d[0]), "+f"(d[1]), "+f"(d[2]), "+f"(d[3])
        : "r"(a[0]), "r"(a[1]), "r"(a[2]), "r"(a[3]), "r"(b[0]), "r"(b[1]));
}

__device__ __forceinline__ void cp_async16(uint32_t dst, const void* src) {
    asm volatile("cp.async.ca.shared.global [%0], [%1], 16;"
        :: "r"(dst), "l"(src));
}

// split two fp32 into packed bf16 hi-word and lo-word (elem0 in low half)
__device__ __forceinline__ void split2(float a, float b, uint32_t& h, uint32_t& l) {
    __nv_bfloat16 ha = __float2bfloat16(a), hb = __float2bfloat16(b);
    float la = a - __bfloat162float(ha), lb = b - __bfloat162float(hb);
    __nv_bfloat16 lA = __float2bfloat16(la), lB = __float2bfloat16(lb);
    h = (uint32_t)__bfloat16_as_ushort(ha) | ((uint32_t)__bfloat16_as_ushort(hb) << 16);
    l = (uint32_t)__bfloat16_as_ushort(lA) | ((uint32_t)__bfloat16_as_ushort(lB) << 16);
}

__device__ __forceinline__ uint32_t pack2(float a, float b) {
    __nv_bfloat16 ha = __float2bfloat16(a), hb = __float2bfloat16(b);
    return (uint32_t)__bfloat16_as_ushort(ha) | ((uint32_t)__bfloat16_as_ushort(hb) << 16);
}

// convert 8 consecutive floats -> uint4 hi + uint4 lo
__device__ __forceinline__ void stage8(const float* s, void* dh, void* dl) {
    uint32_t h[4], l[4];
    #pragma unroll
    for (int p = 0; p < 4; p++) split2(s[2*p], s[2*p+1], h[p], l[p]);
    *(uint4*)dh = make_uint4(h[0], h[1], h[2], h[3]);
    *(uint4*)dl = make_uint4(l[0], l[1], l[2], l[3]);
}

// ---------------------------------------------------------------------------
// Kernel 0: convert 5 weight matrices into bf16 hi/lo, padded stride 136.
// ---------------------------------------------------------------------------
__global__ __launch_bounds__(256) void convw_kernel(
    const float* __restrict__ wq, const float* __restrict__ wk,
    const float* __restrict__ wv, const float* __restrict__ wg,
    const float* __restrict__ wo)
{
    int m = blockIdx.x;
    const float* src = (m == 0) ? wq : (m == 1) ? wk : (m == 2) ? wv : (m == 3) ? wg : wo;
    for (int idx = threadIdx.x; idx < 128 * 64; idx += 256) {
        int r = idx >> 6, cp = (idx & 63) * 2;
        uint32_t h, l;
        split2(src[r * 128 + cp], src[r * 128 + cp + 1], h, l);
        *(uint32_t*)&g_Wh[m][r][cp] = h;
        *(uint32_t*)&g_Wl[m][r][cp] = l;
    }
}

// ---------------------------------------------------------------------------
// GEMM tile geometry: M-tile 64, N 128, block 256 (8 warps): warp = 32m x 32n.
// smem: XH [64][136], XL, WH [128][136], WL = 102 KB -> 2 CTAs/SM
// ---------------------------------------------------------------------------
#define GX_XH 0
#define GX_XL 17408
#define GX_WH 34816
#define GX_WL 69632
#define GX_SMEM 104448

// ---------------------------------------------------------------------------
// Kernel 1: projections. grid = (1024 row-tiles, 4 modes).
// ---------------------------------------------------------------------------
__global__ __launch_bounds__(256) void mma_proj_kernel(
    const float* __restrict__ qx, const float* __restrict__ kvx,
    const float* __restrict__ bg)
{
    extern __shared__ __align__(16) char smem[];
    const int tid = threadIdx.x, w = tid >> 5, lane = tid & 31;
    const int mi = w & 1, nh = w >> 1;
    const int mode = blockIdx.y;
    const int r0 = blockIdx.x * 64;
    const uint32_t sb = smem_u32(smem);

    // prefetch W hi/lo via cp.async (overlaps with X conversion below)
    {
        const char* srcH = (const char*)g_Wh[mode];
        const char* srcL = (const char*)g_Wl[mode];
        for (int i = tid; i < 2176; i += 256) {
            cp_async16(sb + GX_WH + i * 16, srcH + i * 16);
            cp_async16(sb + GX_WL + i * 16, srcL + i * 16);
        }
        asm volatile("cp.async.commit_group;");
    }

    // stage X (64 rows x 128 cols) hi/lo
    {
        const float* X = (mode == 0 || mode == 3) ? qx : kvx;
        int r = tid >> 2, c0 = (tid & 3) * 32;
        const float* src = X + (size_t)(r0 + r) * CIN + c0;
        __nv_bfloat16* dh = (__nv_bfloat16*)(smem + GX_XH) + r * 136 + c0;
        __nv_bfloat16* dl = (__nv_bfloat16*)(smem + GX_XL) + r * 136 + c0;
        float buf[8];
        #pragma unroll
        for (int i = 0; i < 32; i += 8) {
            *(float4*)&buf[0] = *(const float4*)(src + i);
            *(float4*)&buf[4] = *(const float4*)(src + i + 4);
            stage8(buf, dh + i, dl + i);
        }
    }
    asm volatile("cp.async.wait_group 0;" ::: "memory");
    __syncthreads();

    const int lt = lane >> 3, lr = lane & 7;
    const uint32_t a_off = ((uint32_t)(mi * 32 + ((lt & 1) ? 8 : 0) + lr) * 136
                           + ((lt & 2) ? 8 : 0)) * 2;
    const uint32_t b_off = ((uint32_t)(nh * 32 + ((lt & 2) ? 8 : 0) + lr) * 136
                           + ((lt & 1) ? 8 : 0)) * 2;
    const float SCALE = 0.17677669529663687f;

    float acc[2][2][2][4];   // [mf][g][j][4]
    #pragma unroll
    for (int mf = 0; mf < 2; mf++)
        #pragma unroll
        for (int g = 0; g < 2; g++)
            #pragma unroll
            for (int j = 0; j < 2; j++)
                #pragma unroll
                for (int i = 0; i < 4; i++) acc[mf][g][j][i] = 0.f;

    #pragma unroll
    for (int k = 0; k < 8; k++) {
        uint32_t ah[2][4], al[2][4];
        #pragma unroll
        for (int mf = 0; mf < 2; mf++) {
            ldsm_x4(ah[mf], sb + GX_XH + a_off + mf * 4352 + k * 32);
            ldsm_x4(al[mf], sb + GX_XL + a_off + mf * 4352 + k * 32);
        }
        #pragma unroll
        for (int g = 0; g < 2; g++) {
            uint32_t bh[4], bl[4];
            uint32_t ba = sb + GX_WH + b_off + g * 4352 + k * 32;
            ldsm_x4(bh, ba);
            ldsm_x4(bl, ba + (GX_WL - GX_WH));
            #pragma unroll
            for (int mf = 0; mf < 2; mf++) {
                mma_bf16(acc[mf][g][0], ah[mf], bh); mma_bf16(acc[mf][g][1], ah[mf], bh+2);
                mma_bf16(acc[mf][g][0], ah[mf], bl); mma_bf16(acc[mf][g][1], ah[mf], bl+2);
                mma_bf16(acc[mf][g][0], al[mf], bh); mma_bf16(acc[mf][g][1], al[mf], bh+2);
            }
        }
    }

    #pragma unroll
    for (int mf = 0; mf < 2; mf++) {
        const int rlo = r0 + mi * 32 + mf * 16 + (lane >> 2);
        const int rhi = rlo + 8;
        const int n_lo = rlo >> 8, q_lo = rlo & 255;
        const int n_hi = rhi >> 8, q_hi = rhi & 255;
        #pragma unroll
        for (int g = 0; g < 2; g++)
            #pragma unroll
            for (int j = 0; j < 2; j++) {
                int col = nh * 32 + g * 16 + j * 8 + 2 * (lane & 3);
                float* a = acc[mf][g][j];
                if (mode == 2) {
                    int hh = col >> 5, d = col & 31;
                    size_t ilo = ((size_t)(n_lo * NH + hh) * NN + q_lo) * HD + d;
                    size_t ihi = ((size_t)(n_hi * NH + hh) * NN + q_hi) * HD + d;
                    uint32_t vh, vl;
                    split2(a[0], a[1], vh, vl);
                    *(uint32_t*)(g_Vhb + ilo) = vh;
                    *(uint32_t*)(g_Vlb + ilo) = vl;
                    split2(a[2], a[3], vh, vl);
                    *(uint32_t*)(g_Vhb + ihi) = vh;
                    *(uint32_t*)(g_Vlb + ihi) = vl;
                } else if (mode < 2) {
                    float sc = (mode == 0) ? SCALE : 1.f;
                    __nv_bfloat16* dstb = (mode == 0) ? g_Qb : g_Kb;
                    int hh = col >> 5, d = col & 31;
                    size_t ilo = ((size_t)(n_lo * NH + hh) * NN + q_lo) * HD + d;
                    size_t ihi = ((size_t)(n_hi * NH + hh) * NN + q_hi) * HD + d;
                    *(uint32_t*)(dstb + ilo) = pack2(a[0] * sc, a[1] * sc);
                    *(uint32_t*)(dstb + ihi) = pack2(a[2] * sc, a[3] * sc);
                } else {
                    float b0 = bg[col], b1 = bg[col + 1];
                    *(float2*)(g_G + (size_t)rlo * NE + col) = make_float2(
                        1.f / (1.f + __expf(-(a[0] + b0))),
                        1.f / (1.f + __expf(-(a[1] + b1))));
                    *(float2*)(g_G + (size_t)rhi * NE + col) = make_float2(
                        1.f / (1.f + __expf(-(a[2] + b0))),
                        1.f / (1.f + __expf(-(a[3] + b1))));
                }
            }
    }
}

// ---------------------------------------------------------------------------
// Kernel 2: attention. grid=(NH, NN), block=256 (8 warps x 32 q = all 256 q).
// All operand tensors arrive as bf16 -> staged via cp.async, no conversion.
// V kept row-major [key][d] in smem; PV B-fragments via ldmatrix.trans.
// smem: QH [256][40], KH [256][40], VH [256][40], VL [256][40] = 80 KB -> 2 CTA/SM
// ---------------------------------------------------------------------------
#define AT_QH 0
#define AT_KH 20480
#define AT_VH 40960
#define AT_VL 61440
#define AT_SMEM 81920

__global__ __launch_bounds__(256, 2) void mma_attn_kernel(
    const float* __restrict__ mb, const float* __restrict__ tb)
{
    extern __shared__ __align__(16) char smem[];
    const int tid = threadIdx.x, w = tid >> 5, lane = tid & 31;
    const int h = blockIdx.x;
    const int n = blockIdx.y;
    const uint32_t sb = smem_u32(smem);

    // stage Q,K,Vh,Vl rows (row = tid, 64B each) via cp.async
    {
        const size_t base = (size_t)(n * NH + h) * NN * HD;   // halves
        const char* sQ = (const char*)(g_Qb + base) + tid * 64;
        const char* sK = (const char*)(g_Kb + base) + tid * 64;
        const char* sVh = (const char*)(g_Vhb + base) + tid * 64;
        const char* sVl = (const char*)(g_Vlb + base) + tid * 64;
        uint32_t drow = (uint32_t)tid * 80;
        #pragma unroll
        for (int i = 0; i < 4; i++) {
            cp_async16(sb + AT_QH + drow + i * 16, sQ + i * 16);
            cp_async16(sb + AT_KH + drow + i * 16, sK + i * 16);
            cp_async16(sb + AT_VH + drow + i * 16, sVh + i * 16);
            cp_async16(sb + AT_VL + drow + i * 16, sVl + i * 16);
        }
        asm volatile("cp.async.commit_group;");
    }
    asm volatile("cp.async.wait_group 0;" ::: "memory");
    __syncthreads();

    const int lt = lane >> 3, lr = lane & 7;
    const uint32_t bk_off = ((((lt & 2) ? 8 : 0) + lr) * 40 + ((lt & 1) ? 8 : 0)) * 2;
    // trans-V fragment offsets: lane groups map (k-half, d-tile)
    const uint32_t bv_off = (uint32_t)((lt & 1) * 8 + lr) * 80 + (uint32_t)(lt >> 1) * 16;

    // Q fragments: 2 m16 frags (rows w*32 + mf*16 ...), 2 kd halves of d32
    uint32_t aQh[2][2][4];
    #pragma unroll
    for (int mf = 0; mf < 2; mf++) {
        uint32_t aq_off = ((uint32_t)(w * 32 + mf * 16 + ((lt & 1) ? 8 : 0) + lr) * 40
                          + ((lt & 2) ? 8 : 0)) * 2;
        ldsm_x4(aQh[mf][0], sb + AT_QH + aq_off);
        ldsm_x4(aQh[mf][1], sb + AT_QH + aq_off + 32);
    }

    const int qr00 = w * 32 + (lane >> 2);
    const float* mrow = mb + (size_t)n * NN;
    const float* tr00 = tb + ((size_t)h * NN + qr00) * NN;
    const float* tr01 = tr00 + 8 * NN;
    const float* tr10 = tr00 + 16 * NN;
    const float* tr11 = tr00 + 24 * NN;

    float oacc[2][4][4];
    #pragma unroll
    for (int mf = 0; mf < 2; mf++)
        #pragma unroll
        for (int f = 0; f < 4; f++)
            #pragma unroll
            for (int i = 0; i < 4; i++) oacc[mf][f][i] = 0.f;
    float s00 = 0.f, s01 = 0.f, s10 = 0.f, s11 = 0.f;

    #pragma unroll 1
    for (int c = 0; c < 8; c++) {                 // 32-key chunks
        const int kc0 = c * 32;
        float sacc[2][4][4];
        #pragma unroll
        for (int mf = 0; mf < 2; mf++)
            #pragma unroll
            for (int f = 0; f < 4; f++)
                #pragma unroll
                for (int i = 0; i < 4; i++) sacc[mf][f][i] = 0.f;

        // S = Q K^T
        #pragma unroll
        for (int kd = 0; kd < 2; kd++) {
            #pragma unroll
            for (int g = 0; g < 2; g++) {
                uint32_t bh[4];
                ldsm_x4(bh, sb + AT_KH + bk_off + (uint32_t)(kc0 + g * 16) * 80 + kd * 32);
                #pragma unroll
                for (int mf = 0; mf < 2; mf++) {
                    mma_bf16(sacc[mf][2*g],   aQh[mf][kd], bh);
                    mma_bf16(sacc[mf][2*g+1], aQh[mf][kd], bh+2);
                }
            }
        }

        // biases + exp + sums
        #pragma unroll
        for (int f = 0; f < 4; f++) {
            int kcol = kc0 + f * 8 + 2 * (lane & 3);
            float2 mv = *(const float2*)(mrow + kcol);
            float2 t00 = *(const float2*)(tr00 + kcol);
            float2 t01 = *(const float2*)(tr01 + kcol);
            float2 t10 = *(const float2*)(tr10 + kcol);
            float2 t11 = *(const float2*)(tr11 + kcol);
            sacc[0][f][0] = __expf(sacc[0][f][0] + mv.x + t00.x);
            sacc[0][f][1] = __expf(sacc[0][f][1] + mv.y + t00.y);
            sacc[0][f][2] = __expf(sacc[0][f][2] + mv.x + t01.x);
            sacc[0][f][3] = __expf(sacc[0][f][3] + mv.y + t01.y);
            sacc[1][f][0] = __expf(sacc[1][f][0] + mv.x + t10.x);
            sacc[1][f][1] = __expf(sacc[1][f][1] + mv.y + t10.y);
            sacc[1][f][2] = __expf(sacc[1][f][2] + mv.x + t11.x);
            sacc[1][f][3] = __expf(sacc[1][f][3] + mv.y + t11.y);
            s00 += sacc[0][f][0] + sacc[0][f][1];
            s01 += sacc[0][f][2] + sacc[0][f][3];
            s10 += sacc[1][f][0] + sacc[1][f][1];
            s11 += sacc[1][f][2] + sacc[1][f][3];
        }

        // O += P V (3-split), V fragments via ldmatrix.trans from row-major
        #pragma unroll
        for (int kf = 0; kf < 2; kf++) {
            uint32_t ph[2][4], pl[2][4];
            #pragma unroll
            for (int mf = 0; mf < 2; mf++) {
                split2(sacc[mf][2*kf][0],   sacc[mf][2*kf][1],   ph[mf][0], pl[mf][0]);
                split2(sacc[mf][2*kf][2],   sacc[mf][2*kf][3],   ph[mf][1], pl[mf][1]);
                split2(sacc[mf][2*kf+1][0], sacc[mf][2*kf+1][1], ph[mf][2], pl[mf][2]);
                split2(sacc[mf][2*kf+1][2], sacc[mf][2*kf+1][3], ph[mf][3], pl[mf][3]);
            }
            uint32_t krow = (uint32_t)(kc0 + kf * 16) * 80;
            #pragma unroll
            for (int ngd = 0; ngd < 2; ngd++) {
                uint32_t bh[4], bl[4];
                uint32_t ba = sb + AT_VH + krow + bv_off + ngd * 32;
                ldsm_x4_t(bh, ba);
                ldsm_x4_t(bl, ba + (AT_VL - AT_VH));
                #pragma unroll
                for (int mf = 0; mf < 2; mf++) {
                    mma_bf16(oacc[mf][2*ngd],   ph[mf], bh);
                    mma_bf16(oacc[mf][2*ngd+1], ph[mf], bh+2);
                    mma_bf16(oacc[mf][2*ngd],   ph[mf], bl);
                    mma_bf16(oacc[mf][2*ngd+1], ph[mf], bl+2);
                    mma_bf16(oacc[mf][2*ngd],   pl[mf], bh);
                    mma_bf16(oacc[mf][2*ngd+1], pl[mf], bh+2);
                }
            }
        }
    }

    s00 += __shfl_xor_sync(0xffffffffu, s00, 1);
    s00 += __shfl_xor_sync(0xffffffffu, s00, 2);
    s01 += __shfl_xor_sync(0xffffffffu, s01, 1);
    s01 += __shfl_xor_sync(0xffffffffu, s01, 2);
    s10 += __shfl_xor_sync(0xffffffffu, s10, 1);
    s10 += __shfl_xor_sync(0xffffffffu, s10, 2);
    s11 += __shfl_xor_sync(0xffffffffu, s11, 1);
    s11 += __shfl_xor_sync(0xffffffffu, s11, 2);
    float inv[2][2] = {{1.f / s00, 1.f / s01}, {1.f / s10, 1.f / s11}};

    #pragma unroll
    for (int mf = 0; mf < 2; mf++) {
        const int rlo = n * NN + w * 32 + mf * 16 + (lane >> 2);
        const int rhi = rlo + 8;
        #pragma unroll
        for (int f = 0; f < 4; f++) {
            int d = f * 8 + 2 * (lane & 3);
            float2 glo = *(const float2*)(g_G + (size_t)rlo * NE + h * HD + d);
            float2 ghi = *(const float2*)(g_G + (size_t)rhi * NE + h * HD + d);
            *(float2*)(g_O + (size_t)rlo * NE + h * HD + d) = make_float2(
                oacc[mf][f][0] * inv[mf][0] * glo.x,
                oacc[mf][f][1] * inv[mf][0] * glo.y);
            *(float2*)(g_O + (size_t)rhi * NE + h * HD + d) = make_float2(
                oacc[mf][f][2] * inv[mf][1] * ghi.x,
                oacc[mf][f][3] * inv[mf][1] * ghi.y);
        }
    }
}

// ---------------------------------------------------------------------------
// Kernel 3: output projection. grid = 1024, block = 256, warp 32m x 32n.
// ---------------------------------------------------------------------------
__global__ __launch_bounds__(256) void mma_out_kernel(
    const float* __restrict__ bo, float* __restrict__ out)
{
    extern __shared__ __align__(16) char smem[];
    const int tid = threadIdx.x, w = tid >> 5, lane = tid & 31;
    const int mi = w & 1, nh = w >> 1;
    const int r0 = blockIdx.x * 64;
    const uint32_t sb = smem_u32(smem);

    {
        const char* srcH = (const char*)g_Wh[4];
        const char* srcL = (const char*)g_Wl[4];
        for (int i = tid; i < 2176; i += 256) {
            cp_async16(sb + GX_WH + i * 16, srcH + i * 16);
            cp_async16(sb + GX_WL + i * 16, srcL + i * 16);
        }
        asm volatile("cp.async.commit_group;");
    }
    {
        int r = tid >> 2, c0 = (tid & 3) * 32;
        const float* src = g_O + (size_t)(r0 + r) * NE + c0;
        __nv_bfloat16* dh = (__nv_bfloat16*)(smem + GX_XH) + r * 136 + c0;
        __nv_bfloat16* dl = (__nv_bfloat16*)(smem + GX_XL) + r * 136 + c0;
        float buf[8];
        #pragma unroll
        for (int i = 0; i < 32; i += 8) {
            *(float4*)&buf[0] = *(const float4*)(src + i);
            *(float4*)&buf[4] = *(const float4*)(src + i + 4);
            stage8(buf, dh + i, dl + i);
        }
    }
    asm volatile("cp.async.wait_group 0;" ::: "memory");
    __syncthreads();

    const int lt = lane >> 3, lr = lane & 7;
    const uint32_t a_off = ((uint32_t)(mi * 32 + ((lt & 1) ? 8 : 0) + lr) * 136
                           + ((lt & 2) ? 8 : 0)) * 2;
    const uint32_t b_off = ((uint32_t)(nh * 32 + ((lt & 2) ? 8 : 0) + lr) * 136
                           + ((lt & 1) ? 8 : 0)) * 2;

    float acc[2][2][2][4];
    #pragma unroll
    for (int mf = 0; mf < 2; mf++)
        #pragma unroll
        for (int g = 0; g < 2; g++)
            #pragma unroll
            for (int j = 0; j < 2; j++)
                #pragma unroll
                for (int i = 0; i < 4; i++) acc[mf][g][j][i] = 0.f;

    #pragma unroll
    for (int k = 0; k < 8; k++) {
        uint32_t ah[2][4], al[2][4];
        #pragma unroll
        for (int mf = 0; mf < 2; mf++) {
            ldsm_x4(ah[mf], sb + GX_XH + a_off + mf * 4352 + k * 32);
            ldsm_x4(al[mf], sb + GX_XL + a_off + mf * 4352 + k * 32);
        }
        #pragma unroll
        for (int g = 0; g < 2; g++) {
            uint32_t bh[4], bl[4];
            uint32_t ba = sb + GX_WH + b_off + g * 4352 + k * 32;
            ldsm_x4(bh, ba);
            ldsm_x4(bl, ba + (GX_WL - GX_WH));
            #pragma unroll
            for (int mf = 0; mf < 2; mf++) {
                mma_bf16(acc[mf][g][0], ah[mf], bh); mma_bf16(acc[mf][g][1], ah[mf], bh+2);
                mma_bf16(acc[mf][g][0], ah[mf], bl); mma_bf16(acc[mf][g][1], ah[mf], bl+2);
                mma_bf16(acc[mf][g][0], al[mf], bh); mma_bf16(acc[mf][g][1], al[mf], bh+2);
            }
        }
    }

    #pragma unroll
    for (int mf = 0; mf < 2; mf++) {
        const int rlo = r0 + mi * 32 + mf * 16 + (lane >> 2);
        const int rhi = rlo + 8;
        #pragma unroll
        for (int g = 0; g < 2; g++)
            #pragma unroll
            for (int j = 0; j < 2; j++) {
                int cc = nh * 32 + g * 16 + j * 8 + 2 * (lane & 3);
                float b0 = bo[cc], b1 = bo[cc + 1];
                float* a = acc[mf][g][j];
                *(float2*)(out + (size_t)rlo * CIN + cc) = make_float2(a[0] + b0, a[1] + b1);
                *(float2*)(out + (size_t)rhi * CIN + cc) = make_float2(a[2] + b0, a[3] + b1);
            }
    }
}

// ---------------------------------------------------------------------------
extern "C" void kernel_launch(void* const* d_in, const int* in_sizes, int n_in,
                              void* d_out, int out_size)
{
    const float* qx  = (const float*)d_in[0];
    const float* kvx = (const float*)d_in[1];
    const float* mb  = (const float*)d_in[2];
    const float* tb  = (const float*)d_in[3];
    const float* wq  = (const float*)d_in[4];
    const float* wk  = (const float*)d_in[5];
    const float* wv  = (const float*)d_in[6];
    const float* wg  = (const float*)d_in[7];
    const float* bg  = (const float*)d_in[8];
    const float* wo  = (const float*)d_in[9];
    const float* bo  = (const float*)d_in[10];
    float* out = (float*)d_out;

    cudaFuncSetAttribute(mma_proj_kernel, cudaFuncAttributeMaxDynamicSharedMemorySize, GX_SMEM);
    cudaFuncSetAttribute(mma_attn_kernel, cudaFuncAttributeMaxDynamicSharedMemorySize, AT_SMEM);
    cudaFuncSetAttribute(mma_out_kernel,  cudaFuncAttributeMaxDynamicSharedMemorySize, GX_SMEM);

    convw_kernel<<<5, 256>>>(wq, wk, wv, wg, wo);
    mma_proj_kernel<<<dim3(1024, 4), 256, GX_SMEM>>>(qx, kvx, bg);
    mma_attn_kernel<<<dim3(NH, NN), 256, AT_SMEM>>>(mb, tb);
    mma_out_kernel<<<1024, 256, GX_SMEM>>>(bo, out);
}

// round 10
// speedup vs baseline: 3.6279x; 1.0416x over previous
#include <cuda_runtime.h>
#include <cuda_bf16.h>
#include <cstdint>
#include <math.h>

#define NN  256
#define CIN 128
#define NH  4
#define HD  32
#define NE  128

// Scratch (allocation-free rule)
__device__ __align__(16) __nv_bfloat16 g_Qb[NN*NH*NN*HD];   // bf16(scaled q)
__device__ __align__(16) __nv_bfloat16 g_Kb[NN*NH*NN*HD];   // bf16(k)
__device__ __align__(16) __nv_bfloat16 g_Vhb[NN*NH*NN*HD];  // v hi
__device__ __align__(16) __nv_bfloat16 g_Vlb[NN*NH*NN*HD];  // v lo
__device__ float g_G[NN*NN*NE];      // sigmoid gate [rid][e] (fp32 - precision)
__device__ float g_O[NN*NN*NE];      // gated attention out [rid][e]
__device__ __align__(16) __nv_bfloat16 g_Wh[5][128][136];   // weights hi
__device__ __align__(16) __nv_bfloat16 g_Wl[5][128][136];   // weights lo

// ---------------------------------------------------------------------------
// helpers
// ---------------------------------------------------------------------------
__device__ __forceinline__ uint32_t smem_u32(const void* p) {
    uint32_t a;
    asm("{ .reg .u64 t; cvta.to.shared.u64 t, %1; cvt.u32.u64 %0, t; }"
        : "=r"(a) : "l"(p));
    return a;
}

__device__ __forceinline__ void ldsm_x4(uint32_t* r, uint32_t addr) {
    asm volatile("ldmatrix.sync.aligned.m8n8.x4.shared.b16 {%0,%1,%2,%3}, [%4];"
        : "=r"(r[0]), "=r"(r[1]), "=r"(r[2]), "=r"(r[3]) : "r"(addr));
}

__device__ __forceinline__ void ldsm_x4_t(uint32_t* r, uint32_t addr) {
    asm volatile("ldmatrix.sync.aligned.m8n8.x4.trans.shared.b16 {%0,%1,%2,%3}, [%4];"
        : "=r"(r[0]), "=r"(r[1]), "=r"(r[2]), "=r"(r[3]) : "r"(addr));
}

__device__ __forceinline__ void mma_bf16(float* d, const uint32_t* a, const uint32_t* b) {
    asm volatile(
        "mma.sync.aligned.m16n8k16.row.col.f32.bf16.bf16.f32 "
        "{%0,%1,%2,%3}, {%4,%5,%6,%7}, {%8,%9}, {%0,%1,%2,%3};"
        : "+f"(d[0]), "+f"(d[1]), "+f"(d[2]), "+f"(d[3])
        : "r"(a[0]), "r"(a[1]), "r"(a[2]), "r"(a[3]), "r"(b[0]), "r"(b[1]));
}

__device__ __forceinline__ void cp_async16(uint32_t dst, const void* src) {
    asm volatile("cp.async.ca.shared.global [%0], [%1], 16;"
        :: "r"(dst), "l"(src));
}

// split two fp32 into packed bf16 hi-word and lo-word (elem0 in low half)
__device__ __forceinline__ void split2(float a, float b, uint32_t& h, uint32_t& l) {
    __nv_bfloat16 ha = __float2bfloat16(a), hb = __float2bfloat16(b);
    float la = a - __bfloat162float(ha), lb = b - __bfloat162float(hb);
    __nv_bfloat16 lA = __float2bfloat16(la), lB = __float2bfloat16(lb);
    h = (uint32_t)__bfloat16_as_ushort(ha) | ((uint32_t)__bfloat16_as_ushort(hb) << 16);
    l = (uint32_t)__bfloat16_as_ushort(lA) | ((uint32_t)__bfloat16_as_ushort(lB) << 16);
}

__device__ __forceinline__ uint32_t pack2(float a, float b) {
    __nv_bfloat16 ha = __float2bfloat16(a), hb = __float2bfloat16(b);
    return (uint32_t)__bfloat16_as_ushort(ha) | ((uint32_t)__bfloat16_as_ushort(hb) << 16);
}

// convert 8 consecutive floats -> uint4 hi + uint4 lo
__device__ __forceinline__ void stage8(const float* s, void* dh, void* dl) {
    uint32_t h[4], l[4];
    #pragma unroll
    for (int p = 0; p < 4; p++) split2(s[2*p], s[2*p+1], h[p], l[p]);
    *(uint4*)dh = make_uint4(h[0], h[1], h[2], h[3]);
    *(uint4*)dl = make_uint4(l[0], l[1], l[2], l[3]);
}

// convert 8 consecutive floats -> uint4 hi only
__device__ __forceinline__ void stage8h(const float* s, void* dh) {
    uint32_t h[4];
    #pragma unroll
    for (int p = 0; p < 4; p++) {
        __nv_bfloat16 a = __float2bfloat16(s[2*p]), b = __float2bfloat16(s[2*p+1]);
        h[p] = (uint32_t)__bfloat16_as_ushort(a) | ((uint32_t)__bfloat16_as_ushort(b) << 16);
    }
    *(uint4*)dh = make_uint4(h[0], h[1], h[2], h[3]);
}

// ---------------------------------------------------------------------------
// Kernel 0: convert 5 weight matrices into bf16 hi/lo, padded stride 136.
// ---------------------------------------------------------------------------
__global__ __launch_bounds__(256) void convw_kernel(
    const float* __restrict__ wq, const float* __restrict__ wk,
    const float* __restrict__ wv, const float* __restrict__ wg,
    const float* __restrict__ wo)
{
    int m = blockIdx.x;
    const float* src = (m == 0) ? wq : (m == 1) ? wk : (m == 2) ? wv : (m == 3) ? wg : wo;
    for (int idx = threadIdx.x; idx < 128 * 64; idx += 256) {
        int r = idx >> 6, cp = (idx & 63) * 2;
        uint32_t h, l;
        split2(src[r * 128 + cp], src[r * 128 + cp + 1], h, l);
        *(uint32_t*)&g_Wh[m][r][cp] = h;
        *(uint32_t*)&g_Wl[m][r][cp] = l;
    }
}

// ---------------------------------------------------------------------------
// GEMM tile geometry: M-tile 64, N 128, block 256 (8 warps): warp = 32m x 32n.
// smem: XH [64][136], XL, WH [128][136], WL = 102 KB -> 2 CTAs/SM
// ---------------------------------------------------------------------------
#define GX_XH 0
#define GX_XL 17408
#define GX_WH 34816
#define GX_WL 69632
#define GX_SMEM 104448

// ---------------------------------------------------------------------------
// Kernel 1: projections. grid = (1024 row-tiles, 4 modes).
// Modes 0,1 (Q,K): single hh MMA (outputs rounded to bf16 anyway).
// Modes 2,3 (V,gate): full 3-split for fp32-grade accuracy.
// ---------------------------------------------------------------------------
__global__ __launch_bounds__(256) void mma_proj_kernel(
    const float* __restrict__ qx, const float* __restrict__ kvx,
    const float* __restrict__ bg)
{
    extern __shared__ __align__(16) char smem[];
    const int tid = threadIdx.x, w = tid >> 5, lane = tid & 31;
    const int mi = w & 1, nh = w >> 1;
    const int mode = blockIdx.y;
    const bool light = (mode < 2);
    const int r0 = blockIdx.x * 64;
    const uint32_t sb = smem_u32(smem);

    // prefetch W hi (and lo only when needed) via cp.async
    {
        const char* srcH = (const char*)g_Wh[mode];
        const char* srcL = (const char*)g_Wl[mode];
        for (int i = tid; i < 2176; i += 256) {
            cp_async16(sb + GX_WH + i * 16, srcH + i * 16);
            if (!light) cp_async16(sb + GX_WL + i * 16, srcL + i * 16);
        }
        asm volatile("cp.async.commit_group;");
    }

    // stage X (64 rows x 128 cols)
    {
        const float* X = (mode == 0 || mode == 3) ? qx : kvx;
        int r = tid >> 2, c0 = (tid & 3) * 32;
        const float* src = X + (size_t)(r0 + r) * CIN + c0;
        __nv_bfloat16* dh = (__nv_bfloat16*)(smem + GX_XH) + r * 136 + c0;
        __nv_bfloat16* dl = (__nv_bfloat16*)(smem + GX_XL) + r * 136 + c0;
        float buf[8];
        #pragma unroll
        for (int i = 0; i < 32; i += 8) {
            *(float4*)&buf[0] = *(const float4*)(src + i);
            *(float4*)&buf[4] = *(const float4*)(src + i + 4);
            if (light) stage8h(buf, dh + i);
            else       stage8(buf, dh + i, dl + i);
        }
    }
    asm volatile("cp.async.wait_group 0;" ::: "memory");
    __syncthreads();

    const int lt = lane >> 3, lr = lane & 7;
    const uint32_t a_off = ((uint32_t)(mi * 32 + ((lt & 1) ? 8 : 0) + lr) * 136
                           + ((lt & 2) ? 8 : 0)) * 2;
    const uint32_t b_off = ((uint32_t)(nh * 32 + ((lt & 2) ? 8 : 0) + lr) * 136
                           + ((lt & 1) ? 8 : 0)) * 2;
    const float SCALE = 0.17677669529663687f;

    float acc[2][2][2][4];   // [mf][g][j][4]
    #pragma unroll
    for (int mf = 0; mf < 2; mf++)
        #pragma unroll
        for (int g = 0; g < 2; g++)
            #pragma unroll
            for (int j = 0; j < 2; j++)
                #pragma unroll
                for (int i = 0; i < 4; i++) acc[mf][g][j][i] = 0.f;

    if (light) {
        #pragma unroll
        for (int k = 0; k < 8; k++) {
            uint32_t ah[2][4];
            #pragma unroll
            for (int mf = 0; mf < 2; mf++)
                ldsm_x4(ah[mf], sb + GX_XH + a_off + mf * 4352 + k * 32);
            #pragma unroll
            for (int g = 0; g < 2; g++) {
                uint32_t bh[4];
                ldsm_x4(bh, sb + GX_WH + b_off + g * 4352 + k * 32);
                #pragma unroll
                for (int mf = 0; mf < 2; mf++) {
                    mma_bf16(acc[mf][g][0], ah[mf], bh);
                    mma_bf16(acc[mf][g][1], ah[mf], bh+2);
                }
            }
        }
    } else {
        #pragma unroll
        for (int k = 0; k < 8; k++) {
            uint32_t ah[2][4], al[2][4];
            #pragma unroll
            for (int mf = 0; mf < 2; mf++) {
                ldsm_x4(ah[mf], sb + GX_XH + a_off + mf * 4352 + k * 32);
                ldsm_x4(al[mf], sb + GX_XL + a_off + mf * 4352 + k * 32);
            }
            #pragma unroll
            for (int g = 0; g < 2; g++) {
                uint32_t bh[4], bl[4];
                uint32_t ba = sb + GX_WH + b_off + g * 4352 + k * 32;
                ldsm_x4(bh, ba);
                ldsm_x4(bl, ba + (GX_WL - GX_WH));
                #pragma unroll
                for (int mf = 0; mf < 2; mf++) {
                    mma_bf16(acc[mf][g][0], ah[mf], bh); mma_bf16(acc[mf][g][1], ah[mf], bh+2);
                    mma_bf16(acc[mf][g][0], ah[mf], bl); mma_bf16(acc[mf][g][1], ah[mf], bl+2);
                    mma_bf16(acc[mf][g][0], al[mf], bh); mma_bf16(acc[mf][g][1], al[mf], bh+2);
                }
            }
        }
    }

    #pragma unroll
    for (int mf = 0; mf < 2; mf++) {
        const int rlo = r0 + mi * 32 + mf * 16 + (lane >> 2);
        const int rhi = rlo + 8;
        const int n_lo = rlo >> 8, q_lo = rlo & 255;
        const int n_hi = rhi >> 8, q_hi = rhi & 255;
        #pragma unroll
        for (int g = 0; g < 2; g++)
            #pragma unroll
            for (int j = 0; j < 2; j++) {
                int col = nh * 32 + g * 16 + j * 8 + 2 * (lane & 3);
                float* a = acc[mf][g][j];
                if (mode == 2) {
                    int hh = col >> 5, d = col & 31;
                    size_t ilo = ((size_t)(n_lo * NH + hh) * NN + q_lo) * HD + d;
                    size_t ihi = ((size_t)(n_hi * NH + hh) * NN + q_hi) * HD + d;
                    uint32_t vh, vl;
                    split2(a[0], a[1], vh, vl);
                    *(uint32_t*)(g_Vhb + ilo) = vh;
                    *(uint32_t*)(g_Vlb + ilo) = vl;
                    split2(a[2], a[3], vh, vl);
                    *(uint32_t*)(g_Vhb + ihi) = vh;
                    *(uint32_t*)(g_Vlb + ihi) = vl;
                } else if (mode < 2) {
                    float sc = (mode == 0) ? SCALE : 1.f;
                    __nv_bfloat16* dstb = (mode == 0) ? g_Qb : g_Kb;
                    int hh = col >> 5, d = col & 31;
                    size_t ilo = ((size_t)(n_lo * NH + hh) * NN + q_lo) * HD + d;
                    size_t ihi = ((size_t)(n_hi * NH + hh) * NN + q_hi) * HD + d;
                    *(uint32_t*)(dstb + ilo) = pack2(a[0] * sc, a[1] * sc);
                    *(uint32_t*)(dstb + ihi) = pack2(a[2] * sc, a[3] * sc);
                } else {
                    float b0 = bg[col], b1 = bg[col + 1];
                    *(float2*)(g_G + (size_t)rlo * NE + col) = make_float2(
                        1.f / (1.f + __expf(-(a[0] + b0))),
                        1.f / (1.f + __expf(-(a[1] + b1))));
                    *(float2*)(g_G + (size_t)rhi * NE + col) = make_float2(
                        1.f / (1.f + __expf(-(a[2] + b0))),
                        1.f / (1.f + __expf(-(a[3] + b1))));
                }
            }
    }
}

// ---------------------------------------------------------------------------
// Kernel 2: attention. grid=(NH, NN), block=256 (8 warps x 32 q = all 256 q).
// smem: QH [256][40], KH [256][40], VH [256][40], VL [256][40] = 80 KB -> 2 CTA/SM
// ---------------------------------------------------------------------------
#define AT_QH 0
#define AT_KH 20480
#define AT_VH 40960
#define AT_VL 61440
#define AT_SMEM 81920

__global__ __launch_bounds__(256, 2) void mma_attn_kernel(
    const float* __restrict__ mb, const float* __restrict__ tb)
{
    extern __shared__ __align__(16) char smem[];
    const int tid = threadIdx.x, w = tid >> 5, lane = tid & 31;
    const int h = blockIdx.x;
    const int n = blockIdx.y;
    const uint32_t sb = smem_u32(smem);

    // stage Q,K,Vh,Vl rows (row = tid, 64B each) via cp.async
    {
        const size_t base = (size_t)(n * NH + h) * NN * HD;   // halves
        const char* sQ = (const char*)(g_Qb + base) + tid * 64;
        const char* sK = (const char*)(g_Kb + base) + tid * 64;
        const char* sVh = (const char*)(g_Vhb + base) + tid * 64;
        const char* sVl = (const char*)(g_Vlb + base) + tid * 64;
        uint32_t drow = (uint32_t)tid * 80;
        #pragma unroll
        for (int i = 0; i < 4; i++) {
            cp_async16(sb + AT_QH + drow + i * 16, sQ + i * 16);
            cp_async16(sb + AT_KH + drow + i * 16, sK + i * 16);
            cp_async16(sb + AT_VH + drow + i * 16, sVh + i * 16);
            cp_async16(sb + AT_VL + drow + i * 16, sVl + i * 16);
        }
        asm volatile("cp.async.commit_group;");
    }
    asm volatile("cp.async.wait_group 0;" ::: "memory");
    __syncthreads();

    const int lt = lane >> 3, lr = lane & 7;
    const uint32_t bk_off = ((((lt & 2) ? 8 : 0) + lr) * 40 + ((lt & 1) ? 8 : 0)) * 2;
    const uint32_t bv_off = (uint32_t)((lt & 1) * 8 + lr) * 80 + (uint32_t)(lt >> 1) * 16;

    uint32_t aQh[2][2][4];
    #pragma unroll
    for (int mf = 0; mf < 2; mf++) {
        uint32_t aq_off = ((uint32_t)(w * 32 + mf * 16 + ((lt & 1) ? 8 : 0) + lr) * 40
                          + ((lt & 2) ? 8 : 0)) * 2;
        ldsm_x4(aQh[mf][0], sb + AT_QH + aq_off);
        ldsm_x4(aQh[mf][1], sb + AT_QH + aq_off + 32);
    }

    const int qr00 = w * 32 + (lane >> 2);
    const float* mrow = mb + (size_t)n * NN;
    const float* tr00 = tb + ((size_t)h * NN + qr00) * NN;
    const float* tr01 = tr00 + 8 * NN;
    const float* tr10 = tr00 + 16 * NN;
    const float* tr11 = tr00 + 24 * NN;

    float oacc[2][4][4];
    #pragma unroll
    for (int mf = 0; mf < 2; mf++)
        #pragma unroll
        for (int f = 0; f < 4; f++)
            #pragma unroll
            for (int i = 0; i < 4; i++) oacc[mf][f][i] = 0.f;
    float s00 = 0.f, s01 = 0.f, s10 = 0.f, s11 = 0.f;

    #pragma unroll 1
    for (int c = 0; c < 8; c++) {                 // 32-key chunks
        const int kc0 = c * 32;
        float sacc[2][4][4];
        #pragma unroll
        for (int mf = 0; mf < 2; mf++)
            #pragma unroll
            for (int f = 0; f < 4; f++)
                #pragma unroll
                for (int i = 0; i < 4; i++) sacc[mf][f][i] = 0.f;

        // S = Q K^T
        #pragma unroll
        for (int kd = 0; kd < 2; kd++) {
            #pragma unroll
            for (int g = 0; g < 2; g++) {
                uint32_t bh[4];
                ldsm_x4(bh, sb + AT_KH + bk_off + (uint32_t)(kc0 + g * 16) * 80 + kd * 32);
                #pragma unroll
                for (int mf = 0; mf < 2; mf++) {
                    mma_bf16(sacc[mf][2*g],   aQh[mf][kd], bh);
                    mma_bf16(sacc[mf][2*g+1], aQh[mf][kd], bh+2);
                }
            }
        }

        // biases + exp + sums
        #pragma unroll
        for (int f = 0; f < 4; f++) {
            int kcol = kc0 + f * 8 + 2 * (lane & 3);
            float2 mv = *(const float2*)(mrow + kcol);
            float2 t00 = *(const float2*)(tr00 + kcol);
            float2 t01 = *(const float2*)(tr01 + kcol);
            float2 t10 = *(const float2*)(tr10 + kcol);
            float2 t11 = *(const float2*)(tr11 + kcol);
            sacc[0][f][0] = __expf(sacc[0][f][0] + mv.x + t00.x);
            sacc[0][f][1] = __expf(sacc[0][f][1] + mv.y + t00.y);
            sacc[0][f][2] = __expf(sacc[0][f][2] + mv.x + t01.x);
            sacc[0][f][3] = __expf(sacc[0][f][3] + mv.y + t01.y);
            sacc[1][f][0] = __expf(sacc[1][f][0] + mv.x + t10.x);
            sacc[1][f][1] = __expf(sacc[1][f][1] + mv.y + t10.y);
            sacc[1][f][2] = __expf(sacc[1][f][2] + mv.x + t11.x);
            sacc[1][f][3] = __expf(sacc[1][f][3] + mv.y + t11.y);
            s00 += sacc[0][f][0] + sacc[0][f][1];
            s01 += sacc[0][f][2] + sacc[0][f][3];
            s10 += sacc[1][f][0] + sacc[1][f][1];
            s11 += sacc[1][f][2] + sacc[1][f][3];
        }

        // O += P V (3-split), V fragments via ldmatrix.trans from row-major
        #pragma unroll
        for (int kf = 0; kf < 2; kf++) {
            uint32_t ph[2][4], pl[2][4];
            #pragma unroll
            for (int mf = 0; mf < 2; mf++) {
                split2(sacc[mf][2*kf][0],   sacc[mf][2*kf][1],   ph[mf][0], pl[mf][0]);
                split2(sacc[mf][2*kf][2],   sacc[mf][2*kf][3],   ph[mf][1], pl[mf][1]);
                split2(sacc[mf][2*kf+1][0], sacc[mf][2*kf+1][1], ph[mf][2], pl[mf][2]);
                split2(sacc[mf][2*kf+1][2], sacc[mf][2*kf+1][3], ph[mf][3], pl[mf][3]);
            }
            uint32_t krow = (uint32_t)(kc0 + kf * 16) * 80;
            #pragma unroll
            for (int ngd = 0; ngd < 2; ngd++) {
                uint32_t bh[4], bl[4];
                uint32_t ba = sb + AT_VH + krow + bv_off + ngd * 32;
                ldsm_x4_t(bh, ba);
                ldsm_x4_t(bl, ba + (AT_VL - AT_VH));
                #pragma unroll
                for (int mf = 0; mf < 2; mf++) {
                    mma_bf16(oacc[mf][2*ngd],   ph[mf], bh);
                    mma_bf16(oacc[mf][2*ngd+1], ph[mf], bh+2);
                    mma_bf16(oacc[mf][2*ngd],   ph[mf], bl);
                    mma_bf16(oacc[mf][2*ngd+1], ph[mf], bl+2);
                    mma_bf16(oacc[mf][2*ngd],   pl[mf], bh);
                    mma_bf16(oacc[mf][2*ngd+1], pl[mf], bh+2);
                }
            }
        }
    }

    s00 += __shfl_xor_sync(0xffffffffu, s00, 1);
    s00 += __shfl_xor_sync(0xffffffffu, s00, 2);
    s01 += __shfl_xor_sync(0xffffffffu, s01, 1);
    s01 += __shfl_xor_sync(0xffffffffu, s01, 2);
    s10 += __shfl_xor_sync(0xffffffffu, s10, 1);
    s10 += __shfl_xor_sync(0xffffffffu, s10, 2);
    s11 += __shfl_xor_sync(0xffffffffu, s11, 1);
    s11 += __shfl_xor_sync(0xffffffffu, s11, 2);
    float inv[2][2] = {{1.f / s00, 1.f / s01}, {1.f / s10, 1.f / s11}};

    #pragma unroll
    for (int mf = 0; mf < 2; mf++) {
        const int rlo = n * NN + w * 32 + mf * 16 + (lane >> 2);
        const int rhi = rlo + 8;
        #pragma unroll
        for (int f = 0; f < 4; f++) {
            int d = f * 8 + 2 * (lane & 3);
            float2 glo = *(const float2*)(g_G + (size_t)rlo * NE + h * HD + d);
            float2 ghi = *(const float2*)(g_G + (size_t)rhi * NE + h * HD + d);
            *(float2*)(g_O + (size_t)rlo * NE + h * HD + d) = make_float2(
                oacc[mf][f][0] * inv[mf][0] * glo.x,
                oacc[mf][f][1] * inv[mf][0] * glo.y);
            *(float2*)(g_O + (size_t)rhi * NE + h * HD + d) = make_float2(
                oacc[mf][f][2] * inv[mf][1] * ghi.x,
                oacc[mf][f][3] * inv[mf][1] * ghi.y);
        }
    }
}

// ---------------------------------------------------------------------------
// Kernel 3: output projection. grid = 1024, block = 256, warp 32m x 32n.
// ---------------------------------------------------------------------------
__global__ __launch_bounds__(256) void mma_out_kernel(
    const float* __restrict__ bo, float* __restrict__ out)
{
    extern __shared__ __align__(16) char smem[];
    const int tid = threadIdx.x, w = tid >> 5, lane = tid & 31;
    const int mi = w & 1, nh = w >> 1;
    const int r0 = blockIdx.x * 64;
    const uint32_t sb = smem_u32(smem);

    {
        const char* srcH = (const char*)g_Wh[4];
        const char* srcL = (const char*)g_Wl[4];
        for (int i = tid; i < 2176; i += 256) {
            cp_async16(sb + GX_WH + i * 16, srcH + i * 16);
            cp_async16(sb + GX_WL + i * 16, srcL + i * 16);
        }
        asm volatile("cp.async.commit_group;");
    }
    {
        int r = tid >> 2, c0 = (tid & 3) * 32;
        const float* src = g_O + (size_t)(r0 + r) * NE + c0;
        __nv_bfloat16* dh = (__nv_bfloat16*)(smem + GX_XH) + r * 136 + c0;
        __nv_bfloat16* dl = (__nv_bfloat16*)(smem + GX_XL) + r * 136 + c0;
        float buf[8];
        #pragma unroll
        for (int i = 0; i < 32; i += 8) {
            *(float4*)&buf[0] = *(const float4*)(src + i);
            *(float4*)&buf[4] = *(const float4*)(src + i + 4);
            stage8(buf, dh + i, dl + i);
        }
    }
    asm volatile("cp.async.wait_group 0;" ::: "memory");
    __syncthreads();

    const int lt = lane >> 3, lr = lane & 7;
    const uint32_t a_off = ((uint32_t)(mi * 32 + ((lt & 1) ? 8 : 0) + lr) * 136
                           + ((lt & 2) ? 8 : 0)) * 2;
    const uint32_t b_off = ((uint32_t)(nh * 32 + ((lt & 2) ? 8 : 0) + lr) * 136
                           + ((lt & 1) ? 8 : 0)) * 2;

    float acc[2][2][2][4];
    #pragma unroll
    for (int mf = 0; mf < 2; mf++)
        #pragma unroll
        for (int g = 0; g < 2; g++)
            #pragma unroll
            for (int j = 0; j < 2; j++)
                #pragma unroll
                for (int i = 0; i < 4; i++) acc[mf][g][j][i] = 0.f;

    #pragma unroll
    for (int k = 0; k < 8; k++) {
        uint32_t ah[2][4], al[2][4];
        #pragma unroll
        for (int mf = 0; mf < 2; mf++) {
            ldsm_x4(ah[mf], sb + GX_XH + a_off + mf * 4352 + k * 32);
            ldsm_x4(al[mf], sb + GX_XL + a_off + mf * 4352 + k * 32);
        }
        #pragma unroll
        for (int g = 0; g < 2; g++) {
            uint32_t bh[4], bl[4];
            uint32_t ba = sb + GX_WH + b_off + g * 4352 + k * 32;
            ldsm_x4(bh, ba);
            ldsm_x4(bl, ba + (GX_WL - GX_WH));
            #pragma unroll
            for (int mf = 0; mf < 2; mf++) {
                mma_bf16(acc[mf][g][0], ah[mf], bh); mma_bf16(acc[mf][g][1], ah[mf], bh+2);
                mma_bf16(acc[mf][g][0], ah[mf], bl); mma_bf16(acc[mf][g][1], ah[mf], bl+2);
                mma_bf16(acc[mf][g][0], al[mf], bh); mma_bf16(acc[mf][g][1], al[mf], bh+2);
            }
        }
    }

    #pragma unroll
    for (int mf = 0; mf < 2; mf++) {
        const int rlo = r0 + mi * 32 + mf * 16 + (lane >> 2);
        const int rhi = rlo + 8;
        #pragma unroll
        for (int g = 0; g < 2; g++)
            #pragma unroll
            for (int j = 0; j < 2; j++) {
                int cc = nh * 32 + g * 16 + j * 8 + 2 * (lane & 3);
                float b0 = bo[cc], b1 = bo[cc + 1];
                float* a = acc[mf][g][j];
                *(float2*)(out + (size_t)rlo * CIN + cc) = make_float2(a[0] + b0, a[1] + b1);
                *(float2*)(out + (size_t)rhi * CIN + cc) = make_float2(a[2] + b0, a[3] + b1);
            }
    }
}

// ---------------------------------------------------------------------------
extern "C" void kernel_launch(void* const* d_in, const int* in_sizes, int n_in,
                              void* d_out, int out_size)
{
    const float* qx  = (const float*)d_in[0];
    const float* kvx = (const float*)d_in[1];
    const float* mb  = (const float*)d_in[2];
    const float* tb  = (const float*)d_in[3];
    const float* wq  = (const float*)d_in[4];
    const float* wk  = (const float*)d_in[5];
    const float* wv  = (const float*)d_in[6];
    const float* wg  = (const float*)d_in[7];
    const float* bg  = (const float*)d_in[8];
    const float* wo  = (const float*)d_in[9];
    const float* bo  = (const float*)d_in[10];
    float* out = (float*)d_out;

    cudaFuncSetAttribute(mma_proj_kernel, cudaFuncAttributeMaxDynamicSharedMemorySize, GX_SMEM);
    cudaFuncSetAttribute(mma_attn_kernel, cudaFuncAttributeMaxDynamicSharedMemorySize, AT_SMEM);
    cudaFuncSetAttribute(mma_out_kernel,  cudaFuncAttributeMaxDynamicSharedMemorySize, GX_SMEM);

    convw_kernel<<<5, 256>>>(wq, wk, wv, wg, wo);
    mma_proj_kernel<<<dim3(1024, 4), 256, GX_SMEM>>>(qx, kvx, bg);
    mma_attn_kernel<<<dim3(NH, NN), 256, AT_SMEM>>>(mb, tb);
    mma_out_kernel<<<1024, 256, GX_SMEM>>>(bo, out);
}